// round 13
// baseline (speedup 1.0000x reference)
#include <cuda_runtime.h>
#include <cuda_bf16.h>
#include <cuda_fp16.h>
#include <math.h>
#include <stdint.h>

#define Bc 2
#define Sc 2048
#define Dc 1024
#define Hc 16
#define Lc 6
#define Fc 4096
#define Vc 32000
#define DHc 64
#define MR (Bc*Sc)   // 4096 rows

// ---------------------------------------------------------------------------
// scratch (static device globals; no allocations allowed)
// 16-bit buffers are untyped bit-containers (bf16* alias, hold fp16 bits)
// ---------------------------------------------------------------------------
__device__ float g_x[MR*Dc];
__device__ __nv_bfloat16 g_qkv[6*MR*Dc];   // qhi,qlo,khi,klo,vhi,vlo (fp16 bits)
__device__ __nv_bfloat16 g_ahi[MR*Fc];
__device__ __nv_bfloat16 g_alo[MR*Fc];
__device__ __nv_bfloat16 g_bhi[MR*Fc];
__device__ __nv_bfloat16 g_blo[MR*Fc];
#define WPL 12582912   // elems per layer (4*D*D + D*F + F*D)
__device__ __nv_bfloat16 g_whi[Lc*WPL];    // all weights fp16 bits
__device__ __nv_bfloat16 g_wlo[Lc*WPL];
__device__ __half g_thi[Vc*Dc];
__device__ __half g_tlo[Vc*Dc];

// ---------------------------------------------------------------------------
// helpers
// ---------------------------------------------------------------------------
__device__ __forceinline__ uint32_t s2u(const void* ptr) {
    uint32_t a;
    asm("{ .reg .u64 t; cvta.to.shared.u64 t, %1; cvt.u32.u64 %0, t; }"
        : "=r"(a) : "l"(ptr));
    return a;
}
__device__ __forceinline__ void cpasync16(uint32_t dst, const void* src) {
    asm volatile("cp.async.cg.shared.global [%0], [%1], 16;" :: "r"(dst), "l"(src));
}
__device__ __forceinline__ void ldm4(uint32_t* r, uint32_t addr) {
    asm volatile("ldmatrix.sync.aligned.m8n8.x4.shared.b16 {%0,%1,%2,%3}, [%4];"
                 : "=r"(r[0]), "=r"(r[1]), "=r"(r[2]), "=r"(r[3]) : "r"(addr));
}
__device__ __forceinline__ void ldm4t(uint32_t* r, uint32_t addr) {
    asm volatile("ldmatrix.sync.aligned.m8n8.x4.trans.shared.b16 {%0,%1,%2,%3}, [%4];"
                 : "=r"(r[0]), "=r"(r[1]), "=r"(r[2]), "=r"(r[3]) : "r"(addr));
}
template<bool H>
__device__ __forceinline__ void mma16(float* d, const uint32_t* a, const uint32_t* b) {
    if (H)
        asm volatile(
            "mma.sync.aligned.m16n8k16.row.col.f32.f16.f16.f32 "
            "{%0,%1,%2,%3}, {%4,%5,%6,%7}, {%8,%9}, {%0,%1,%2,%3};"
            : "+f"(d[0]), "+f"(d[1]), "+f"(d[2]), "+f"(d[3])
            : "r"(a[0]), "r"(a[1]), "r"(a[2]), "r"(a[3]), "r"(b[0]), "r"(b[1]));
    else
        asm volatile(
            "mma.sync.aligned.m16n8k16.row.col.f32.bf16.bf16.f32 "
            "{%0,%1,%2,%3}, {%4,%5,%6,%7}, {%8,%9}, {%0,%1,%2,%3};"
            : "+f"(d[0]), "+f"(d[1]), "+f"(d[2]), "+f"(d[3])
            : "r"(a[0]), "r"(a[1]), "r"(a[2]), "r"(a[3]), "r"(b[0]), "r"(b[1]));
}
__device__ __forceinline__ void split2h(float v, __half* h, __half* l) {
    __half hh = __float2half(v);
    *h = hh;
    *l = __float2half(v - __half2float(hh));
}
__device__ __forceinline__ void pk2h(float x, float y, uint32_t& hi, uint32_t& lo) {
    __half xh = __float2half(x), yh = __float2half(y);
    __half xl = __float2half(x - __half2float(xh));
    __half yl = __float2half(y - __half2float(yh));
    hi = ((uint32_t)__half_as_ushort(yh) << 16) | __half_as_ushort(xh);
    lo = ((uint32_t)__half_as_ushort(yl) << 16) | __half_as_ushort(xl);
}
// fast 2^y on the FMA pipe (y <= 0), err ~2e-6
__device__ __forceinline__ float ex2(float y) {
    y = fmaxf(y, -126.f);
    float fn = y + 12582912.f;
    int n = __float_as_int(fn) - 0x4B400000;
    float r = y - (fn - 12582912.f);
    float p = 1.3333558e-3f;
    p = fmaf(p, r, 9.6181291e-3f);
    p = fmaf(p, r, 5.5504109e-2f);
    p = fmaf(p, r, 2.4022651e-1f);
    p = fmaf(p, r, 6.9314718e-1f);
    p = fmaf(p, r, 1.0f);
    return p * __int_as_float((n + 127) << 23);
}
__device__ __forceinline__ uint32_t swz(uint32_t off) {
    return off ^ ((off >> 3) & 0x70);
}
__device__ __forceinline__ float gelu_f(float v) {
    return 0.5f * v * (1.0f + erff(v * 0.70710678118654752f));
}

// ---------------------------------------------------------------------------
// fp16 2-term split MMA GEMM: C = (Ah+Al)@Bh^T. K-chunk 64, SW128 smem,
// 3-stage pipeline (single barrier/chunk), templated WN (32 or 64).
// ---------------------------------------------------------------------------
#define T16 16384                       // one 128x64 16-bit tile (128B rows)

template<int BROWS>
__device__ __forceinline__ void load_stageG(
    const __nv_bfloat16* A0, const __nv_bfloat16* A1,
    const __nv_bfloat16* B0,
    int K, int k0, uint32_t dbase, int tid) {
#pragma unroll
    for (int t = 0; t < 2; t++) {
        const __nv_bfloat16* s = t ? A1 : A0;
#pragma unroll
        for (int u = 0; u < 4; u++) {
            int id = u * 256 + tid;
            int row = id >> 3, c = id & 7;
            cpasync16(dbase + t * T16 + swz(row * 128 + c * 16),
                      s + (size_t)row * K + k0 + c * 8);
        }
    }
#pragma unroll
    for (int u = 0; u < BROWS / 32; u++) {
        int id = u * 256 + tid;
        int row = id >> 3, c = id & 7;
        cpasync16(dbase + 2 * T16 + swz(row * 128 + c * 16),
                  B0 + (size_t)row * K + k0 + c * 8);
    }
}

template<bool GELU, bool OUT16, int WN>
__global__ __launch_bounds__(256, 1)
void gemm_t(const __nv_bfloat16* __restrict__ Ahi, const __nv_bfloat16* __restrict__ Alo,
            const __nv_bfloat16* __restrict__ Bhi,
            const float* __restrict__ bias, const float* __restrict__ bias2,
            const float* __restrict__ bias3, const float* __restrict__ res,
            float* __restrict__ C, __nv_bfloat16* __restrict__ Chi,
            __nv_bfloat16* __restrict__ Clo, int M, int N, int K, int oseg) {
    constexpr int BROWS = 4 * WN;
    constexpr int NTT = WN / 8;
    constexpr int STAGE = (256 + BROWS) * 128;
    extern __shared__ char smem[];
    const uint32_t sbase = s2u(smem);
    const int tid = threadIdx.x;
    const int warp = tid >> 5, lane = tid & 31;
    const int bm = blockIdx.y * 128, bn = blockIdx.x * BROWS;
    const int wm = (warp >> 2) * 64, wn = (warp & 3) * WN;

    float acc[4][NTT][4];
#pragma unroll
    for (int i = 0; i < 4; i++)
#pragma unroll
        for (int j = 0; j < NTT; j++)
#pragma unroll
            for (int q = 0; q < 4; q++) acc[i][j][q] = 0.f;

    const __nv_bfloat16* A0 = Ahi + (size_t)bm * K;
    const __nv_bfloat16* A1 = Alo + (size_t)bm * K;
    const __nv_bfloat16* B0 = Bhi + (size_t)bn * K;

    const int nch = K >> 6;
    load_stageG<BROWS>(A0, A1, B0, K, 0, sbase, tid);
    asm volatile("cp.async.commit_group;" ::: "memory");
    if (nch > 1) {
        load_stageG<BROWS>(A0, A1, B0, K, 64, sbase + STAGE, tid);
        asm volatile("cp.async.commit_group;" ::: "memory");
    }

    const int g = lane >> 3, r = lane & 7;
    const int a_row = r + (g & 1) * 8;
    const int a_cb  = (g >> 1) * 16;
    const int b_row = (g >> 1) * 8 + r;
    const int b_cb  = (g & 1) * 16;

    for (int c = 0; c < nch; c++) {
        if (c == nch - 1) asm volatile("cp.async.wait_group 0;" ::: "memory");
        else              asm volatile("cp.async.wait_group 1;" ::: "memory");
        __syncthreads();

        uint32_t base = sbase + (c % 3) * STAGE;
#pragma unroll
        for (int ks = 0; ks < 4; ks++) {
            const int kb = ks * 32;
            uint32_t ah[4][4], al[4][4], bh[NTT][2];
#pragma unroll
            for (int mt = 0; mt < 4; mt++) {
                uint32_t ad = base + swz((wm + mt * 16 + a_row) * 128 + kb + a_cb);
                ldm4(ah[mt], ad);
                ldm4(al[mt], ad + T16);
            }
#pragma unroll
            for (int p = 0; p < WN / 16; p++) {
                uint32_t bd = base + 2 * T16 + swz((wn + p * 16 + b_row) * 128 + kb + b_cb);
                uint32_t t4[4];
                ldm4(t4, bd);
                bh[2 * p][0] = t4[0]; bh[2 * p][1] = t4[1];
                bh[2 * p + 1][0] = t4[2]; bh[2 * p + 1][1] = t4[3];
            }
#pragma unroll
            for (int mt = 0; mt < 4; mt++)
#pragma unroll
                for (int nt = 0; nt < NTT; nt++) {
                    mma16<true>(acc[mt][nt], ah[mt], bh[nt]);
                    mma16<true>(acc[mt][nt], al[mt], bh[nt]);
                }
        }
        if (c + 2 < nch) {
            load_stageG<BROWS>(A0, A1, B0, K, (c + 2) * 64,
                               sbase + ((c + 2) % 3) * STAGE, tid);
            asm volatile("cp.async.commit_group;" ::: "memory");
        }
    }

    // ---- epilogue
    __nv_bfloat16 *chi = Chi, *clo = Clo;
    int ost = N, bnl = bn;
    if (oseg) {
        int t = bn / oseg;
        bnl = bn - t * oseg;
        ost = oseg;
        chi = Chi + (size_t)(2 * t) * M * oseg;
        clo = Chi + (size_t)(2 * t + 1) * M * oseg;
    }
#pragma unroll
    for (int mt = 0; mt < 4; mt++) {
        int r0 = bm + wm + mt * 16 + (lane >> 2);
#pragma unroll
        for (int nt = 0; nt < NTT; nt++) {
            int ccg = bn + wn + nt * 8 + (lane & 3) * 2;
            int ccl = bnl + wn + nt * 8 + (lane & 3) * 2;
            const float* bsel = bias;
            int bidx = ccg;
            if (bias2) {
                if (ccg >= 2 * Dc)      bsel = bias3;
                else if (ccg >= Dc)     bsel = bias2;
                bidx = ccg & (Dc - 1);
            }
            float b0 = bsel ? bsel[bidx] : 0.f, b1 = bsel ? bsel[bidx + 1] : 0.f;
            float v0 = acc[mt][nt][0] + b0, v1 = acc[mt][nt][1] + b1;
            float v2 = acc[mt][nt][2] + b0, v3 = acc[mt][nt][3] + b1;
            if (GELU) {
                v0 = gelu_f(v0); v1 = gelu_f(v1);
                v2 = gelu_f(v2); v3 = gelu_f(v3);
            }
            if (chi) {
                uint32_t h01, l01, h23, l23;
                pk2h(v0, v1, h01, l01);
                pk2h(v2, v3, h23, l23);
                *(uint32_t*)&chi[(size_t)r0 * ost + ccl] = h01;
                *(uint32_t*)&clo[(size_t)r0 * ost + ccl] = l01;
                *(uint32_t*)&chi[(size_t)(r0 + 8) * ost + ccl] = h23;
                *(uint32_t*)&clo[(size_t)(r0 + 8) * ost + ccl] = l23;
            } else {
                if (res) {
                    v0 += res[(size_t)r0 * N + ccg];       v1 += res[(size_t)r0 * N + ccg + 1];
                    v2 += res[(size_t)(r0 + 8) * N + ccg]; v3 += res[(size_t)(r0 + 8) * N + ccg + 1];
                }
                *(float2*)&C[(size_t)r0 * N + ccg] = make_float2(v0, v1);
                *(float2*)&C[(size_t)(r0 + 8) * N + ccg] = make_float2(v2, v3);
            }
        }
    }
}

#define SMEM_W32 (3*(256+128)*128)     // 147456
#define SMEM_W64 (3*(256+256)*128)     // 196608

// ---------------------------------------------------------------------------
// MMA flash attention (fp16, 3-term exact-split): block = (qt 64, h, b), 4 warps.
// ---------------------------------------------------------------------------
#define ATT_STAGE 32768
#define ATT_SMEM (2*ATT_STAGE)

__global__ __launch_bounds__(128, 2)
void attn_mma(const __nv_bfloat16* __restrict__ qhi, const __nv_bfloat16* __restrict__ qlo,
              const __nv_bfloat16* __restrict__ khi, const __nv_bfloat16* __restrict__ klo,
              const __nv_bfloat16* __restrict__ vhi, const __nv_bfloat16* __restrict__ vlo,
              __nv_bfloat16* __restrict__ ohi, __nv_bfloat16* __restrict__ olo) {
    extern __shared__ char sm[];
    const uint32_t sb = s2u(sm);
    const int qt = blockIdx.x, h = blockIdx.y, b = blockIdx.z;
    const int tid = threadIdx.x, warp = tid >> 5, lane = tid & 31;
    const int g = lane >> 3, r = lane & 7;
    const int a_row = r + (g & 1) * 8, a_cb = (g >> 1) * 16;
    const int b_row = (g >> 1) * 8 + r, b_cb = (g & 1) * 16;
    const size_t hoff = (size_t)h * 64;
    const size_t rowbase = (size_t)(b * Sc) * Dc;

#pragma unroll
    for (int t = 0; t < 2; t++) {
        const __nv_bfloat16* src = (t ? qlo : qhi) + rowbase + (size_t)(qt * 64) * Dc + hoff;
#pragma unroll
        for (int u = 0; u < 4; u++) {
            int id = u * 128 + tid;
            int row = id >> 3, c16 = id & 7;
            uint4 val = *(const uint4*)((const char*)(src + (size_t)row * Dc) + c16 * 16);
            *(uint4*)(sm + t * 8192 + swz(row * 128 + c16 * 16)) = val;
        }
    }
    __syncthreads();
    uint32_t qh_[4][4], ql_[4][4];
#pragma unroll
    for (int ks = 0; ks < 4; ks++) {
        uint32_t ad = sb + swz((warp * 16 + a_row) * 128 + ks * 32 + a_cb);
        ldm4(qh_[ks], ad);
        ldm4(ql_[ks], ad + 8192);
    }
    __syncthreads();

    float O[8][4];
#pragma unroll
    for (int i = 0; i < 8; i++)
#pragma unroll
        for (int j = 0; j < 4; j++) O[i][j] = 0.f;
    float m2[2] = {-1e30f, -1e30f};
    float lsum[2] = {0.f, 0.f};

    const __nv_bfloat16* srcs[4] = {khi, klo, vhi, vlo};
#define LOAD_KV(S, KT) do { \
        size_t base_ = rowbase + (size_t)((KT) * 64) * Dc + hoff; \
        uint32_t dst_ = sb + (S) * ATT_STAGE; \
        _Pragma("unroll") \
        for (int t = 0; t < 4; t++) { \
            _Pragma("unroll") \
            for (int u = 0; u < 4; u++) { \
                int id = u * 128 + tid; \
                int row = id >> 3, c16 = id & 7; \
                cpasync16(dst_ + t * 8192 + swz(row * 128 + c16 * 16), \
                          (const char*)(srcs[t] + base_ + (size_t)row * Dc) + c16 * 16); \
            } \
        } \
        asm volatile("cp.async.commit_group;" ::: "memory"); \
    } while (0)

    LOAD_KV(0, 0);

    for (int kt = 0; kt <= qt; kt++) {
        if (kt < qt) {
            LOAD_KV((kt + 1) & 1, kt + 1);
            asm volatile("cp.async.wait_group 1;" ::: "memory");
        } else {
            asm volatile("cp.async.wait_group 0;" ::: "memory");
        }
        __syncthreads();
        const uint32_t kb_ = sb + (kt & 1) * ATT_STAGE;

        float S[8][4];
#pragma unroll
        for (int i = 0; i < 8; i++)
#pragma unroll
            for (int j = 0; j < 4; j++) S[i][j] = 0.f;
#pragma unroll
        for (int ks = 0; ks < 4; ks++) {
#pragma unroll
            for (int p = 0; p < 4; p++) {
                uint32_t t4h[4], t4l[4];
                uint32_t bd = kb_ + swz((p * 16 + b_row) * 128 + ks * 32 + b_cb);
                ldm4(t4h, bd);
                ldm4(t4l, bd + 8192);
                uint32_t bh0[2] = {t4h[0], t4h[1]}, bh1[2] = {t4h[2], t4h[3]};
                uint32_t bl0[2] = {t4l[0], t4l[1]}, bl1[2] = {t4l[2], t4l[3]};
                mma16<true>(S[2 * p],     qh_[ks], bh0);
                mma16<true>(S[2 * p],     qh_[ks], bl0);
                mma16<true>(S[2 * p],     ql_[ks], bh0);
                mma16<true>(S[2 * p + 1], qh_[ks], bh1);
                mma16<true>(S[2 * p + 1], qh_[ks], bl1);
                mma16<true>(S[2 * p + 1], ql_[ks], bh1);
            }
        }
        const float SC = 0.18033688f;
#pragma unroll
        for (int i = 0; i < 8; i++)
#pragma unroll
            for (int j = 0; j < 4; j++) S[i][j] *= SC;
        if (kt == qt) {
            int rr = warp * 16 + (lane >> 2);
#pragma unroll
            for (int nt = 0; nt < 8; nt++) {
                int cc = nt * 8 + (lane & 3) * 2;
                if (cc     > rr)     S[nt][0] = -1e30f;
                if (cc + 1 > rr)     S[nt][1] = -1e30f;
                if (cc     > rr + 8) S[nt][2] = -1e30f;
                if (cc + 1 > rr + 8) S[nt][3] = -1e30f;
            }
        }
        float mx0 = -1e30f, mx1 = -1e30f;
#pragma unroll
        for (int nt = 0; nt < 8; nt++) {
            mx0 = fmaxf(mx0, fmaxf(S[nt][0], S[nt][1]));
            mx1 = fmaxf(mx1, fmaxf(S[nt][2], S[nt][3]));
        }
        mx0 = fmaxf(mx0, __shfl_xor_sync(0xffffffff, mx0, 1));
        mx0 = fmaxf(mx0, __shfl_xor_sync(0xffffffff, mx0, 2));
        mx1 = fmaxf(mx1, __shfl_xor_sync(0xffffffff, mx1, 1));
        mx1 = fmaxf(mx1, __shfl_xor_sync(0xffffffff, mx1, 2));
        float mn0 = fmaxf(m2[0], mx0), mn1 = fmaxf(m2[1], mx1);
        float al0 = ex2(m2[0] - mn0), al1 = ex2(m2[1] - mn1);
        m2[0] = mn0; m2[1] = mn1;
        float s0 = 0.f, s1 = 0.f;
#pragma unroll
        for (int nt = 0; nt < 8; nt++) {
            S[nt][0] = ex2(S[nt][0] - mn0); s0 += S[nt][0];
            S[nt][1] = ex2(S[nt][1] - mn0); s0 += S[nt][1];
            S[nt][2] = ex2(S[nt][2] - mn1); s1 += S[nt][2];
            S[nt][3] = ex2(S[nt][3] - mn1); s1 += S[nt][3];
        }
        s0 += __shfl_xor_sync(0xffffffff, s0, 1);
        s0 += __shfl_xor_sync(0xffffffff, s0, 2);
        s1 += __shfl_xor_sync(0xffffffff, s1, 1);
        s1 += __shfl_xor_sync(0xffffffff, s1, 2);
        lsum[0] = lsum[0] * al0 + s0;
        lsum[1] = lsum[1] * al1 + s1;
#pragma unroll
        for (int nt = 0; nt < 8; nt++) {
            O[nt][0] *= al0; O[nt][1] *= al0;
            O[nt][2] *= al1; O[nt][3] *= al1;
        }
        const uint32_t vb = kb_ + 16384;
#pragma unroll
        for (int ks = 0; ks < 4; ks++) {
            uint32_t pah[4], pal[4];
            pk2h(S[2 * ks][0],     S[2 * ks][1],     pah[0], pal[0]);
            pk2h(S[2 * ks][2],     S[2 * ks][3],     pah[1], pal[1]);
            pk2h(S[2 * ks + 1][0], S[2 * ks + 1][1], pah[2], pal[2]);
            pk2h(S[2 * ks + 1][2], S[2 * ks + 1][3], pah[3], pal[3]);
#pragma unroll
            for (int dg = 0; dg < 4; dg++) {
                uint32_t th[4], tl[4];
                uint32_t vd = vb + swz((ks * 16 + (lane & 15)) * 128 + dg * 32 + (lane >> 4) * 16);
                ldm4t(th, vd);
                ldm4t(tl, vd + 8192);
                uint32_t bh0[2] = {th[0], th[1]}, bh1[2] = {th[2], th[3]};
                uint32_t bl0[2] = {tl[0], tl[1]}, bl1[2] = {tl[2], tl[3]};
                mma16<true>(O[2 * dg],     pah, bh0);
                mma16<true>(O[2 * dg],     pah, bl0);
                mma16<true>(O[2 * dg],     pal, bh0);
                mma16<true>(O[2 * dg + 1], pah, bh1);
                mma16<true>(O[2 * dg + 1], pah, bl1);
                mma16<true>(O[2 * dg + 1], pal, bh1);
            }
        }
        __syncthreads();
    }

    float inv0 = 1.f / lsum[0], inv1 = 1.f / lsum[1];
    int r0 = qt * 64 + warp * 16 + (lane >> 2);
#pragma unroll
    for (int nt = 0; nt < 8; nt++) {
        int cc = nt * 8 + (lane & 3) * 2;
        size_t o0 = rowbase + (size_t)r0 * Dc + hoff + cc;
        size_t o1 = o0 + (size_t)8 * Dc;
        uint32_t h01, l01, h23, l23;
        pk2h(O[nt][0] * inv0, O[nt][1] * inv0, h01, l01);
        pk2h(O[nt][2] * inv1, O[nt][3] * inv1, h23, l23);
        *(uint32_t*)&ohi[o0] = h01; *(uint32_t*)&olo[o0] = l01;
        *(uint32_t*)&ohi[o1] = h23; *(uint32_t*)&olo[o1] = l23;
    }
}

// ---------------------------------------------------------------------------
// prep kernels (batched over layer x matrix via blockIdx.z)
// ---------------------------------------------------------------------------
__device__ __forceinline__ void wtrans_body(const float* W, __half* hi, __half* lo,
                                            int K, int N) {
    __shared__ float t[32][33];
    int n0 = blockIdx.x * 32, k0 = blockIdx.y * 32;
    int tx = threadIdx.x, ty = threadIdx.y;
#pragma unroll
    for (int r = 0; r < 4; r++)
        t[ty + r * 8][tx] = W[(size_t)(k0 + ty + r * 8) * N + n0 + tx];
    __syncthreads();
#pragma unroll
    for (int r = 0; r < 4; r++) {
        int a = ty + r * 8;
        float v = t[tx][a];
        size_t o = (size_t)(n0 + a) * K + k0 + tx;
        split2h(v, hi + o, lo + o);
    }
}

// 4 square [D,D] matrices x Lc layers; z = l*4 + m
__global__ void wtrans_sq(const float* __restrict__ Wq, const float* __restrict__ Wk,
                          const float* __restrict__ Wv, const float* __restrict__ Wo,
                          __nv_bfloat16* __restrict__ whi, __nv_bfloat16* __restrict__ wlo) {
    int z = blockIdx.z, l = z >> 2, m = z & 3;
    const float* srcs[4] = {Wq, Wk, Wv, Wo};
    const float* W = srcs[m] + (size_t)l * Dc * Dc;
    size_t off = (size_t)l * WPL + (size_t)m * 1048576;
    wtrans_body(W, (__half*)(whi + off), (__half*)(wlo + off), Dc, Dc);
}
// Wup [D,F] -> [F,D]; z = layer
__global__ void wtrans_up(const float* __restrict__ Wup,
                          __nv_bfloat16* __restrict__ whi, __nv_bfloat16* __restrict__ wlo) {
    int l = blockIdx.z;
    size_t off = (size_t)l * WPL + 4194304;
    wtrans_body(Wup + (size_t)l * Dc * Fc, (__half*)(whi + off), (__half*)(wlo + off), Dc, Fc);
}
// Wdown [F,D] -> [D,F]; z = layer
__global__ void wtrans_dn(const float* __restrict__ Wdown,
                          __nv_bfloat16* __restrict__ whi, __nv_bfloat16* __restrict__ wlo) {
    int l = blockIdx.z;
    size_t off = (size_t)l * WPL + 8388608;
    wtrans_body(Wdown + (size_t)l * Fc * Dc, (__half*)(whi + off), (__half*)(wlo + off), Fc, Dc);
}

__global__ void split_kernel_h(const float* __restrict__ in,
                               __half* __restrict__ hi,
                               __half* __restrict__ lo, int n) {
    int i = blockIdx.x * 256 + threadIdx.x;
    if (i < n) split2h(in[i], &hi[i], &lo[i]);
}

__global__ void embed_kernel(const int* __restrict__ ids,
                             const float* __restrict__ tok,
                             const float* __restrict__ pos,
                             float* __restrict__ x) {
    int row = blockIdx.x;
    int s = row % Sc;
    int id = ids[row];
    const float* tr = tok + (size_t)id * Dc;
    const float* pr = pos + (size_t)s * Dc;
    float* xr = x + (size_t)row * Dc;
    for (int d = threadIdx.x; d < Dc; d += blockDim.x) xr[d] = tr[d] + pr[d];
}

__global__ void ln_kernel(const float* __restrict__ x,
                          const float* __restrict__ w, const float* __restrict__ b,
                          __half* __restrict__ yhi, __half* __restrict__ ylo) {
    int row = blockIdx.x;
    const float* xr = x + (size_t)row * Dc;
    __shared__ float r1[256], r2[256];
    float s = 0.f, s2 = 0.f;
    for (int d = threadIdx.x; d < Dc; d += 256) {
        float v = xr[d];
        s += v; s2 += v * v;
    }
    r1[threadIdx.x] = s; r2[threadIdx.x] = s2;
    __syncthreads();
    for (int st = 128; st > 0; st >>= 1) {
        if (threadIdx.x < st) {
            r1[threadIdx.x] += r1[threadIdx.x + st];
            r2[threadIdx.x] += r2[threadIdx.x + st];
        }
        __syncthreads();
    }
    float mean = r1[0] * (1.0f / Dc);
    float var = r2[0] * (1.0f / Dc) - mean * mean;
    float rstd = rsqrtf(var + 1e-5f);
    for (int d = threadIdx.x; d < Dc; d += 256) {
        float v = (xr[d] - mean) * rstd * w[d] + b[d];
        size_t o = (size_t)row * Dc + d;
        split2h(v, yhi + o, ylo + o);
    }
}

// ---------------------------------------------------------------------------
// launcher
// ---------------------------------------------------------------------------
extern "C" void kernel_launch(void* const* d_in, const int* in_sizes, int n_in,
                              void* d_out, int out_size) {
    const int*   ids   = (const int*)d_in[0];
    const float* tok   = (const float*)d_in[1];
    const float* pos   = (const float*)d_in[2];
    const float* Wq    = (const float*)d_in[3];
    const float* bq    = (const float*)d_in[4];
    const float* Wk    = (const float*)d_in[5];
    const float* bk    = (const float*)d_in[6];
    const float* Wv    = (const float*)d_in[7];
    const float* bv    = (const float*)d_in[8];
    const float* Wo    = (const float*)d_in[9];
    const float* bo    = (const float*)d_in[10];
    const float* ln1w  = (const float*)d_in[11];
    const float* ln1b  = (const float*)d_in[12];
    const float* ln2w  = (const float*)d_in[13];
    const float* ln2b  = (const float*)d_in[14];
    const float* Wup   = (const float*)d_in[15];
    const float* bup   = (const float*)d_in[16];
    const float* Wdown = (const float*)d_in[17];
    const float* bdown = (const float*)d_in[18];
    const float* fnw   = (const float*)d_in[19];
    const float* fnb   = (const float*)d_in[20];
    float* out = (float*)d_out;

    float *x;
    __nv_bfloat16 *qkv, *ahi, *alo, *bhi, *blo, *whi, *wlo;
    __half *thi, *tlo;
    cudaGetSymbolAddress((void**)&x, g_x);
    cudaGetSymbolAddress((void**)&qkv, g_qkv);
    cudaGetSymbolAddress((void**)&ahi, g_ahi);
    cudaGetSymbolAddress((void**)&alo, g_alo);
    cudaGetSymbolAddress((void**)&bhi, g_bhi);
    cudaGetSymbolAddress((void**)&blo, g_blo);
    cudaGetSymbolAddress((void**)&whi, g_whi);
    cudaGetSymbolAddress((void**)&wlo, g_wlo);
    cudaGetSymbolAddress((void**)&thi, g_thi);
    cudaGetSymbolAddress((void**)&tlo, g_tlo);
    __nv_bfloat16 *qhi = qkv,              *qlo = qkv + (size_t)MR * Dc;
    __nv_bfloat16 *khi = qkv + 2ull*MR*Dc, *klo = qkv + 3ull*MR*Dc;
    __nv_bfloat16 *vhi = qkv + 4ull*MR*Dc, *vlo = qkv + 5ull*MR*Dc;

    cudaFuncSetAttribute(gemm_t<false,true,64>,  cudaFuncAttributeMaxDynamicSharedMemorySize, SMEM_W64);
    cudaFuncSetAttribute(gemm_t<true,true,64>,   cudaFuncAttributeMaxDynamicSharedMemorySize, SMEM_W64);
    cudaFuncSetAttribute(gemm_t<false,false,32>, cudaFuncAttributeMaxDynamicSharedMemorySize, SMEM_W32);
    cudaFuncSetAttribute(gemm_t<false,false,64>, cudaFuncAttributeMaxDynamicSharedMemorySize, SMEM_W64);
    cudaFuncSetAttribute(attn_mma, cudaFuncAttributeMaxDynamicSharedMemorySize, ATT_SMEM);

    const dim3 tb32(32, 8);

    embed_kernel<<<MR, 256>>>(ids, tok, pos, x);
    // batched weight conversion: 3 launches total
    wtrans_sq<<<dim3(Dc / 32, Dc / 32, 4 * Lc), tb32>>>(Wq, Wk, Wv, Wo, whi, wlo);
    wtrans_up<<<dim3(Fc / 32, Dc / 32, Lc), tb32>>>(Wup, whi, wlo);
    wtrans_dn<<<dim3(Dc / 32, Fc / 32, Lc), tb32>>>(Wdown, whi, wlo);
    split_kernel_h<<<(Vc * Dc + 255) / 256, 256>>>(tok, thi, tlo, Vc * Dc);

    const dim3 gmQKV(3 * Dc / 256, MR / 128);   // 12 x 32 (WN=64)
    const dim3 gmD(Dc / 128, MR / 128);         // 8 x 32  (WN=32)
    const dim3 gmF(Fc / 256, MR / 128);         // 16 x 32 (WN=64)
    const dim3 gmD2(Dc / 256, MR / 128);        // 4 x 32  (WN=64)
    const dim3 gmV2(Vc / 256, MR / 128);        // 125 x 32 (WN=64)
    const dim3 gA(Sc / 64, Hc, Bc);

    for (int l = 0; l < Lc; l++) {
        size_t lb = (size_t)l * WPL;
        ln_kernel<<<MR, 256>>>(x, ln1w + l * Dc, ln1b + l * Dc, (__half*)ahi, (__half*)alo);
        gemm_t<false,true,64><<<gmQKV, 256, SMEM_W64>>>(
            ahi, alo, whi + lb, bq + l * Dc, bk + l * Dc, bv + l * Dc, nullptr,
            nullptr, qkv, nullptr, MR, 3 * Dc, Dc, Dc);
        attn_mma<<<gA, 128, ATT_SMEM>>>(qhi, qlo, khi, klo, vhi, vlo, ahi, alo);
        gemm_t<false,false,32><<<gmD, 256, SMEM_W32>>>(
            ahi, alo, whi + lb + 3145728, bo + l * Dc, nullptr, nullptr, x,
            x, nullptr, nullptr, MR, Dc, Dc, 0);
        ln_kernel<<<MR, 256>>>(x, ln2w + l * Dc, ln2b + l * Dc, (__half*)ahi, (__half*)alo);
        gemm_t<true,true,64><<<gmF, 256, SMEM_W64>>>(
            ahi, alo, whi + lb + 4194304, bup + l * Fc, nullptr, nullptr, nullptr,
            nullptr, bhi, blo, MR, Fc, Dc, 0);
        gemm_t<false,false,64><<<gmD2, 256, SMEM_W64>>>(
            bhi, blo, whi + lb + 8388608, bdown + l * Dc, nullptr, nullptr, x,
            x, nullptr, nullptr, MR, Dc, Fc, 0);
    }

    ln_kernel<<<MR, 256>>>(x, fnw, fnb, (__half*)ahi, (__half*)alo);
    gemm_t<false,false,64><<<gmV2, 256, SMEM_W64>>>(
        ahi, alo, (const __nv_bfloat16*)thi,
        nullptr, nullptr, nullptr, nullptr, out, nullptr, nullptr, MR, Vc, Dc, 0);
}

// round 14
// speedup vs baseline: 1.0927x; 1.0927x over previous
#include <cuda_runtime.h>
#include <cuda_bf16.h>
#include <cuda_fp16.h>
#include <math.h>
#include <stdint.h>

#define Bc 2
#define Sc 2048
#define Dc 1024
#define Hc 16
#define Lc 6
#define Fc 4096
#define Vc 32000
#define DHc 64
#define MR (Bc*Sc)   // 4096 rows

// ---------------------------------------------------------------------------
// scratch (static device globals; no allocations allowed)
// 16-bit buffers are untyped bit-containers (bf16* alias, hold fp16 bits)
// ---------------------------------------------------------------------------
__device__ float g_x[MR*Dc];
__device__ __nv_bfloat16 g_qkv[6*MR*Dc];   // qhi,qlo,khi,klo,vhi,vlo (fp16 bits)
__device__ __nv_bfloat16 g_ahi[MR*Fc];
__device__ __nv_bfloat16 g_alo[MR*Fc];
__device__ __nv_bfloat16 g_bhi[MR*Fc];
__device__ __nv_bfloat16 g_blo[MR*Fc];
#define WPL 12582912   // elems per layer (4*D*D + D*F + F*D)
__device__ __nv_bfloat16 g_whi[Lc*WPL];    // all weights fp16 bits
__device__ __nv_bfloat16 g_wlo[Lc*WPL];
__device__ __half g_thi[Vc*Dc];
__device__ __half g_tlo[Vc*Dc];

// ---------------------------------------------------------------------------
// helpers
// ---------------------------------------------------------------------------
__device__ __forceinline__ uint32_t s2u(const void* ptr) {
    uint32_t a;
    asm("{ .reg .u64 t; cvta.to.shared.u64 t, %1; cvt.u32.u64 %0, t; }"
        : "=r"(a) : "l"(ptr));
    return a;
}
__device__ __forceinline__ void cpasync16(uint32_t dst, const void* src) {
    asm volatile("cp.async.cg.shared.global [%0], [%1], 16;" :: "r"(dst), "l"(src));
}
__device__ __forceinline__ void ldm4(uint32_t* r, uint32_t addr) {
    asm volatile("ldmatrix.sync.aligned.m8n8.x4.shared.b16 {%0,%1,%2,%3}, [%4];"
                 : "=r"(r[0]), "=r"(r[1]), "=r"(r[2]), "=r"(r[3]) : "r"(addr));
}
__device__ __forceinline__ void ldm4t(uint32_t* r, uint32_t addr) {
    asm volatile("ldmatrix.sync.aligned.m8n8.x4.trans.shared.b16 {%0,%1,%2,%3}, [%4];"
                 : "=r"(r[0]), "=r"(r[1]), "=r"(r[2]), "=r"(r[3]) : "r"(addr));
}
__device__ __forceinline__ void mma16h(float* d, const uint32_t* a, const uint32_t* b) {
    asm volatile(
        "mma.sync.aligned.m16n8k16.row.col.f32.f16.f16.f32 "
        "{%0,%1,%2,%3}, {%4,%5,%6,%7}, {%8,%9}, {%0,%1,%2,%3};"
        : "+f"(d[0]), "+f"(d[1]), "+f"(d[2]), "+f"(d[3])
        : "r"(a[0]), "r"(a[1]), "r"(a[2]), "r"(a[3]), "r"(b[0]), "r"(b[1]));
}
__device__ __forceinline__ void split2h(float v, __half* h, __half* l) {
    __half hh = __float2half(v);
    *h = hh;
    *l = __float2half(v - __half2float(hh));
}
__device__ __forceinline__ void pk2h(float x, float y, uint32_t& hi, uint32_t& lo) {
    __half xh = __float2half(x), yh = __float2half(y);
    __half xl = __float2half(x - __half2float(xh));
    __half yl = __float2half(y - __half2float(yh));
    hi = ((uint32_t)__half_as_ushort(yh) << 16) | __half_as_ushort(xh);
    lo = ((uint32_t)__half_as_ushort(yl) << 16) | __half_as_ushort(xl);
}
// fast 2^y on the FMA pipe (y <= 0), err ~2e-6
__device__ __forceinline__ float ex2(float y) {
    y = fmaxf(y, -126.f);
    float fn = y + 12582912.f;
    int n = __float_as_int(fn) - 0x4B400000;
    float r = y - (fn - 12582912.f);
    float p = 1.3333558e-3f;
    p = fmaf(p, r, 9.6181291e-3f);
    p = fmaf(p, r, 5.5504109e-2f);
    p = fmaf(p, r, 2.4022651e-1f);
    p = fmaf(p, r, 6.9314718e-1f);
    p = fmaf(p, r, 1.0f);
    return p * __int_as_float((n + 127) << 23);
}
__device__ __forceinline__ uint32_t swz(uint32_t off) {
    return off ^ ((off >> 3) & 0x70);
}
__device__ __forceinline__ float gelu_f(float v) {
    return 0.5f * v * (1.0f + erff(v * 0.70710678118654752f));
}

// ---------------------------------------------------------------------------
// fp16 split MMA GEMM: C = (Ah[+Al])@Bh^T. K-chunk 64, SW128 smem,
// 3-stage pipeline (single barrier/chunk). TWOA: include Al term.
// WN = warp-N width (32 -> block 128x128, 64 -> block 128x256).
// ---------------------------------------------------------------------------
#define T16 16384                       // one 128x64 16-bit tile (128B rows)

template<int NA, int BROWS>
__device__ __forceinline__ void load_stageG(
    const __nv_bfloat16* A0, const __nv_bfloat16* A1,
    const __nv_bfloat16* B0,
    int K, int k0, uint32_t dbase, int tid) {
#pragma unroll
    for (int t = 0; t < NA; t++) {
        const __nv_bfloat16* s = t ? A1 : A0;
#pragma unroll
        for (int u = 0; u < 4; u++) {
            int id = u * 256 + tid;
            int row = id >> 3, c = id & 7;
            cpasync16(dbase + t * T16 + swz(row * 128 + c * 16),
                      s + (size_t)row * K + k0 + c * 8);
        }
    }
#pragma unroll
    for (int u = 0; u < BROWS / 32; u++) {
        int id = u * 256 + tid;
        int row = id >> 3, c = id & 7;
        cpasync16(dbase + NA * T16 + swz(row * 128 + c * 16),
                  B0 + (size_t)row * K + k0 + c * 8);
    }
}

template<bool TWOA, bool GELU, bool OUT16, int WN>
__global__ __launch_bounds__(256, 1)
void gemm_t(const __nv_bfloat16* __restrict__ Ahi, const __nv_bfloat16* __restrict__ Alo,
            const __nv_bfloat16* __restrict__ Bhi,
            const float* __restrict__ bias, const float* __restrict__ bias2,
            const float* __restrict__ bias3, const float* __restrict__ res,
            float* __restrict__ C, __nv_bfloat16* __restrict__ Chi,
            __nv_bfloat16* __restrict__ Clo, int M, int N, int K, int oseg) {
    constexpr int NA = TWOA ? 2 : 1;
    constexpr int BROWS = 4 * WN;
    constexpr int NTT = WN / 8;
    constexpr int STAGE = (NA * 128 + BROWS) * 128;
    extern __shared__ char smem[];
    const uint32_t sbase = s2u(smem);
    const int tid = threadIdx.x;
    const int warp = tid >> 5, lane = tid & 31;
    const int bm = blockIdx.y * 128, bn = blockIdx.x * BROWS;
    const int wm = (warp >> 2) * 64, wn = (warp & 3) * WN;

    float acc[4][NTT][4];
#pragma unroll
    for (int i = 0; i < 4; i++)
#pragma unroll
        for (int j = 0; j < NTT; j++)
#pragma unroll
            for (int q = 0; q < 4; q++) acc[i][j][q] = 0.f;

    const __nv_bfloat16* A0 = Ahi + (size_t)bm * K;
    const __nv_bfloat16* A1 = Alo + (size_t)bm * K;
    const __nv_bfloat16* B0 = Bhi + (size_t)bn * K;

    const int nch = K >> 6;
    load_stageG<NA, BROWS>(A0, A1, B0, K, 0, sbase, tid);
    asm volatile("cp.async.commit_group;" ::: "memory");
    if (nch > 1) {
        load_stageG<NA, BROWS>(A0, A1, B0, K, 64, sbase + STAGE, tid);
        asm volatile("cp.async.commit_group;" ::: "memory");
    }

    const int g = lane >> 3, r = lane & 7;
    const int a_row = r + (g & 1) * 8;
    const int a_cb  = (g >> 1) * 16;
    const int b_row = (g >> 1) * 8 + r;
    const int b_cb  = (g & 1) * 16;

    for (int c = 0; c < nch; c++) {
        if (c == nch - 1) asm volatile("cp.async.wait_group 0;" ::: "memory");
        else              asm volatile("cp.async.wait_group 1;" ::: "memory");
        __syncthreads();

        uint32_t base = sbase + (c % 3) * STAGE;
#pragma unroll
        for (int ks = 0; ks < 4; ks++) {
            const int kb = ks * 32;
            uint32_t ah[4][4], al[4][4], bh[NTT][2];
#pragma unroll
            for (int mt = 0; mt < 4; mt++) {
                uint32_t ad = base + swz((wm + mt * 16 + a_row) * 128 + kb + a_cb);
                ldm4(ah[mt], ad);
                if (TWOA) ldm4(al[mt], ad + T16);
            }
#pragma unroll
            for (int p = 0; p < WN / 16; p++) {
                uint32_t bd = base + NA * T16 + swz((wn + p * 16 + b_row) * 128 + kb + b_cb);
                uint32_t t4[4];
                ldm4(t4, bd);
                bh[2 * p][0] = t4[0]; bh[2 * p][1] = t4[1];
                bh[2 * p + 1][0] = t4[2]; bh[2 * p + 1][1] = t4[3];
            }
#pragma unroll
            for (int mt = 0; mt < 4; mt++)
#pragma unroll
                for (int nt = 0; nt < NTT; nt++) {
                    mma16h(acc[mt][nt], ah[mt], bh[nt]);
                    if (TWOA) mma16h(acc[mt][nt], al[mt], bh[nt]);
                }
        }
        if (c + 2 < nch) {
            load_stageG<NA, BROWS>(A0, A1, B0, K, (c + 2) * 64,
                                   sbase + ((c + 2) % 3) * STAGE, tid);
            asm volatile("cp.async.commit_group;" ::: "memory");
        }
    }

    // ---- epilogue
    __nv_bfloat16 *chi = Chi, *clo = Clo;
    int ost = N, bnl = bn;
    if (oseg) {
        int t = bn / oseg;
        bnl = bn - t * oseg;
        ost = oseg;
        chi = Chi + (size_t)(2 * t) * M * oseg;
        clo = Chi + (size_t)(2 * t + 1) * M * oseg;
    }
#pragma unroll
    for (int mt = 0; mt < 4; mt++) {
        int r0 = bm + wm + mt * 16 + (lane >> 2);
#pragma unroll
        for (int nt = 0; nt < NTT; nt++) {
            int ccg = bn + wn + nt * 8 + (lane & 3) * 2;
            int ccl = bnl + wn + nt * 8 + (lane & 3) * 2;
            const float* bsel = bias;
            int bidx = ccg;
            if (bias2) {
                if (ccg >= 2 * Dc)      bsel = bias3;
                else if (ccg >= Dc)     bsel = bias2;
                bidx = ccg & (Dc - 1);
            }
            float b0 = bsel ? bsel[bidx] : 0.f, b1 = bsel ? bsel[bidx + 1] : 0.f;
            float v0 = acc[mt][nt][0] + b0, v1 = acc[mt][nt][1] + b1;
            float v2 = acc[mt][nt][2] + b0, v3 = acc[mt][nt][3] + b1;
            if (GELU) {
                v0 = gelu_f(v0); v1 = gelu_f(v1);
                v2 = gelu_f(v2); v3 = gelu_f(v3);
            }
            if (chi) {
                uint32_t h01, l01, h23, l23;
                pk2h(v0, v1, h01, l01);
                pk2h(v2, v3, h23, l23);
                *(uint32_t*)&chi[(size_t)r0 * ost + ccl] = h01;
                *(uint32_t*)&clo[(size_t)r0 * ost + ccl] = l01;
                *(uint32_t*)&chi[(size_t)(r0 + 8) * ost + ccl] = h23;
                *(uint32_t*)&clo[(size_t)(r0 + 8) * ost + ccl] = l23;
            } else {
                if (res) {
                    v0 += res[(size_t)r0 * N + ccg];       v1 += res[(size_t)r0 * N + ccg + 1];
                    v2 += res[(size_t)(r0 + 8) * N + ccg]; v3 += res[(size_t)(r0 + 8) * N + ccg + 1];
                }
                *(float2*)&C[(size_t)r0 * N + ccg] = make_float2(v0, v1);
                *(float2*)&C[(size_t)(r0 + 8) * N + ccg] = make_float2(v2, v3);
            }
        }
    }
}

#define SMEM_A2W32 (3*(256+128)*128)   // 147456
#define SMEM_A2W64 (3*(256+256)*128)   // 196608
#define SMEM_A1W64 (3*(128+256)*128)   // 147456

// ---------------------------------------------------------------------------
// MMA flash attention (fp16, 3-term exact-split): block = (qt 64, h, b), 4 warps.
// ---------------------------------------------------------------------------
#define ATT_STAGE 32768
#define ATT_SMEM (2*ATT_STAGE)

__global__ __launch_bounds__(128, 2)
void attn_mma(const __nv_bfloat16* __restrict__ qhi, const __nv_bfloat16* __restrict__ qlo,
              const __nv_bfloat16* __restrict__ khi, const __nv_bfloat16* __restrict__ klo,
              const __nv_bfloat16* __restrict__ vhi, const __nv_bfloat16* __restrict__ vlo,
              __nv_bfloat16* __restrict__ ohi, __nv_bfloat16* __restrict__ olo) {
    extern __shared__ char sm[];
    const uint32_t sb = s2u(sm);
    const int qt = blockIdx.x, h = blockIdx.y, b = blockIdx.z;
    const int tid = threadIdx.x, warp = tid >> 5, lane = tid & 31;
    const int g = lane >> 3, r = lane & 7;
    const int a_row = r + (g & 1) * 8, a_cb = (g >> 1) * 16;
    const int b_row = (g >> 1) * 8 + r, b_cb = (g & 1) * 16;
    const size_t hoff = (size_t)h * 64;
    const size_t rowbase = (size_t)(b * Sc) * Dc;

#pragma unroll
    for (int t = 0; t < 2; t++) {
        const __nv_bfloat16* src = (t ? qlo : qhi) + rowbase + (size_t)(qt * 64) * Dc + hoff;
#pragma unroll
        for (int u = 0; u < 4; u++) {
            int id = u * 128 + tid;
            int row = id >> 3, c16 = id & 7;
            uint4 val = *(const uint4*)((const char*)(src + (size_t)row * Dc) + c16 * 16);
            *(uint4*)(sm + t * 8192 + swz(row * 128 + c16 * 16)) = val;
        }
    }
    __syncthreads();
    uint32_t qh_[4][4], ql_[4][4];
#pragma unroll
    for (int ks = 0; ks < 4; ks++) {
        uint32_t ad = sb + swz((warp * 16 + a_row) * 128 + ks * 32 + a_cb);
        ldm4(qh_[ks], ad);
        ldm4(ql_[ks], ad + 8192);
    }
    __syncthreads();

    float O[8][4];
#pragma unroll
    for (int i = 0; i < 8; i++)
#pragma unroll
        for (int j = 0; j < 4; j++) O[i][j] = 0.f;
    float m2[2] = {-1e30f, -1e30f};
    float lsum[2] = {0.f, 0.f};

    const __nv_bfloat16* srcs[4] = {khi, klo, vhi, vlo};
#define LOAD_KV(S, KT) do { \
        size_t base_ = rowbase + (size_t)((KT) * 64) * Dc + hoff; \
        uint32_t dst_ = sb + (S) * ATT_STAGE; \
        _Pragma("unroll") \
        for (int t = 0; t < 4; t++) { \
            _Pragma("unroll") \
            for (int u = 0; u < 4; u++) { \
                int id = u * 128 + tid; \
                int row = id >> 3, c16 = id & 7; \
                cpasync16(dst_ + t * 8192 + swz(row * 128 + c16 * 16), \
                          (const char*)(srcs[t] + base_ + (size_t)row * Dc) + c16 * 16); \
            } \
        } \
        asm volatile("cp.async.commit_group;" ::: "memory"); \
    } while (0)

    LOAD_KV(0, 0);

    for (int kt = 0; kt <= qt; kt++) {
        if (kt < qt) {
            LOAD_KV((kt + 1) & 1, kt + 1);
            asm volatile("cp.async.wait_group 1;" ::: "memory");
        } else {
            asm volatile("cp.async.wait_group 0;" ::: "memory");
        }
        __syncthreads();
        const uint32_t kb_ = sb + (kt & 1) * ATT_STAGE;

        float S[8][4];
#pragma unroll
        for (int i = 0; i < 8; i++)
#pragma unroll
            for (int j = 0; j < 4; j++) S[i][j] = 0.f;
#pragma unroll
        for (int ks = 0; ks < 4; ks++) {
#pragma unroll
            for (int p = 0; p < 4; p++) {
                uint32_t t4h[4], t4l[4];
                uint32_t bd = kb_ + swz((p * 16 + b_row) * 128 + ks * 32 + b_cb);
                ldm4(t4h, bd);
                ldm4(t4l, bd + 8192);
                uint32_t bh0[2] = {t4h[0], t4h[1]}, bh1[2] = {t4h[2], t4h[3]};
                uint32_t bl0[2] = {t4l[0], t4l[1]}, bl1[2] = {t4l[2], t4l[3]};
                mma16h(S[2 * p],     qh_[ks], bh0);
                mma16h(S[2 * p],     qh_[ks], bl0);
                mma16h(S[2 * p],     ql_[ks], bh0);
                mma16h(S[2 * p + 1], qh_[ks], bh1);
                mma16h(S[2 * p + 1], qh_[ks], bl1);
                mma16h(S[2 * p + 1], ql_[ks], bh1);
            }
        }
        const float SC = 0.18033688f;
#pragma unroll
        for (int i = 0; i < 8; i++)
#pragma unroll
            for (int j = 0; j < 4; j++) S[i][j] *= SC;
        if (kt == qt) {
            int rr = warp * 16 + (lane >> 2);
#pragma unroll
            for (int nt = 0; nt < 8; nt++) {
                int cc = nt * 8 + (lane & 3) * 2;
                if (cc     > rr)     S[nt][0] = -1e30f;
                if (cc + 1 > rr)     S[nt][1] = -1e30f;
                if (cc     > rr + 8) S[nt][2] = -1e30f;
                if (cc + 1 > rr + 8) S[nt][3] = -1e30f;
            }
        }
        float mx0 = -1e30f, mx1 = -1e30f;
#pragma unroll
        for (int nt = 0; nt < 8; nt++) {
            mx0 = fmaxf(mx0, fmaxf(S[nt][0], S[nt][1]));
            mx1 = fmaxf(mx1, fmaxf(S[nt][2], S[nt][3]));
        }
        mx0 = fmaxf(mx0, __shfl_xor_sync(0xffffffff, mx0, 1));
        mx0 = fmaxf(mx0, __shfl_xor_sync(0xffffffff, mx0, 2));
        mx1 = fmaxf(mx1, __shfl_xor_sync(0xffffffff, mx1, 1));
        mx1 = fmaxf(mx1, __shfl_xor_sync(0xffffffff, mx1, 2));
        float mn0 = fmaxf(m2[0], mx0), mn1 = fmaxf(m2[1], mx1);
        float al0 = ex2(m2[0] - mn0), al1 = ex2(m2[1] - mn1);
        m2[0] = mn0; m2[1] = mn1;
        float s0 = 0.f, s1 = 0.f;
#pragma unroll
        for (int nt = 0; nt < 8; nt++) {
            S[nt][0] = ex2(S[nt][0] - mn0); s0 += S[nt][0];
            S[nt][1] = ex2(S[nt][1] - mn0); s0 += S[nt][1];
            S[nt][2] = ex2(S[nt][2] - mn1); s1 += S[nt][2];
            S[nt][3] = ex2(S[nt][3] - mn1); s1 += S[nt][3];
        }
        s0 += __shfl_xor_sync(0xffffffff, s0, 1);
        s0 += __shfl_xor_sync(0xffffffff, s0, 2);
        s1 += __shfl_xor_sync(0xffffffff, s1, 1);
        s1 += __shfl_xor_sync(0xffffffff, s1, 2);
        lsum[0] = lsum[0] * al0 + s0;
        lsum[1] = lsum[1] * al1 + s1;
#pragma unroll
        for (int nt = 0; nt < 8; nt++) {
            O[nt][0] *= al0; O[nt][1] *= al0;
            O[nt][2] *= al1; O[nt][3] *= al1;
        }
        const uint32_t vb = kb_ + 16384;
#pragma unroll
        for (int ks = 0; ks < 4; ks++) {
            uint32_t pah[4], pal[4];
            pk2h(S[2 * ks][0],     S[2 * ks][1],     pah[0], pal[0]);
            pk2h(S[2 * ks][2],     S[2 * ks][3],     pah[1], pal[1]);
            pk2h(S[2 * ks + 1][0], S[2 * ks + 1][1], pah[2], pal[2]);
            pk2h(S[2 * ks + 1][2], S[2 * ks + 1][3], pah[3], pal[3]);
#pragma unroll
            for (int dg = 0; dg < 4; dg++) {
                uint32_t th[4], tl[4];
                uint32_t vd = vb + swz((ks * 16 + (lane & 15)) * 128 + dg * 32 + (lane >> 4) * 16);
                ldm4t(th, vd);
                ldm4t(tl, vd + 8192);
                uint32_t bh0[2] = {th[0], th[1]}, bh1[2] = {th[2], th[3]};
                uint32_t bl0[2] = {tl[0], tl[1]}, bl1[2] = {tl[2], tl[3]};
                mma16h(O[2 * dg],     pah, bh0);
                mma16h(O[2 * dg],     pah, bl0);
                mma16h(O[2 * dg],     pal, bh0);
                mma16h(O[2 * dg + 1], pah, bh1);
                mma16h(O[2 * dg + 1], pah, bl1);
                mma16h(O[2 * dg + 1], pal, bh1);
            }
        }
        __syncthreads();
    }

    float inv0 = 1.f / lsum[0], inv1 = 1.f / lsum[1];
    int r0 = qt * 64 + warp * 16 + (lane >> 2);
#pragma unroll
    for (int nt = 0; nt < 8; nt++) {
        int cc = nt * 8 + (lane & 3) * 2;
        size_t o0 = rowbase + (size_t)r0 * Dc + hoff + cc;
        size_t o1 = o0 + (size_t)8 * Dc;
        uint32_t h01, l01, h23, l23;
        pk2h(O[nt][0] * inv0, O[nt][1] * inv0, h01, l01);
        pk2h(O[nt][2] * inv1, O[nt][3] * inv1, h23, l23);
        *(uint32_t*)&ohi[o0] = h01; *(uint32_t*)&olo[o0] = l01;
        *(uint32_t*)&ohi[o1] = h23; *(uint32_t*)&olo[o1] = l23;
    }
}

// ---------------------------------------------------------------------------
// prep kernels (batched over layer x matrix via blockIdx.z)
// ---------------------------------------------------------------------------
__device__ __forceinline__ void wtrans_body(const float* W, __half* hi, __half* lo,
                                            int K, int N) {
    __shared__ float t[32][33];
    int n0 = blockIdx.x * 32, k0 = blockIdx.y * 32;
    int tx = threadIdx.x, ty = threadIdx.y;
#pragma unroll
    for (int r = 0; r < 4; r++)
        t[ty + r * 8][tx] = W[(size_t)(k0 + ty + r * 8) * N + n0 + tx];
    __syncthreads();
#pragma unroll
    for (int r = 0; r < 4; r++) {
        int a = ty + r * 8;
        float v = t[tx][a];
        size_t o = (size_t)(n0 + a) * K + k0 + tx;
        split2h(v, hi + o, lo + o);
    }
}

__global__ void wtrans_sq(const float* __restrict__ Wq, const float* __restrict__ Wk,
                          const float* __restrict__ Wv, const float* __restrict__ Wo,
                          __nv_bfloat16* __restrict__ whi, __nv_bfloat16* __restrict__ wlo) {
    int z = blockIdx.z, l = z >> 2, m = z & 3;
    const float* srcs[4] = {Wq, Wk, Wv, Wo};
    const float* W = srcs[m] + (size_t)l * Dc * Dc;
    size_t off = (size_t)l * WPL + (size_t)m * 1048576;
    wtrans_body(W, (__half*)(whi + off), (__half*)(wlo + off), Dc, Dc);
}
__global__ void wtrans_up(const float* __restrict__ Wup,
                          __nv_bfloat16* __restrict__ whi, __nv_bfloat16* __restrict__ wlo) {
    int l = blockIdx.z;
    size_t off = (size_t)l * WPL + 4194304;
    wtrans_body(Wup + (size_t)l * Dc * Fc, (__half*)(whi + off), (__half*)(wlo + off), Dc, Fc);
}
__global__ void wtrans_dn(const float* __restrict__ Wdown,
                          __nv_bfloat16* __restrict__ whi, __nv_bfloat16* __restrict__ wlo) {
    int l = blockIdx.z;
    size_t off = (size_t)l * WPL + 8388608;
    wtrans_body(Wdown + (size_t)l * Fc * Dc, (__half*)(whi + off), (__half*)(wlo + off), Fc, Dc);
}

__global__ void split_kernel_h(const float* __restrict__ in,
                               __half* __restrict__ hi,
                               __half* __restrict__ lo, int n) {
    int i = blockIdx.x * 256 + threadIdx.x;
    if (i < n) split2h(in[i], &hi[i], &lo[i]);
}

__global__ void embed_kernel(const int* __restrict__ ids,
                             const float* __restrict__ tok,
                             const float* __restrict__ pos,
                             float* __restrict__ x) {
    int row = blockIdx.x;
    int s = row % Sc;
    int id = ids[row];
    const float* tr = tok + (size_t)id * Dc;
    const float* pr = pos + (size_t)s * Dc;
    float* xr = x + (size_t)row * Dc;
    for (int d = threadIdx.x; d < Dc; d += blockDim.x) xr[d] = tr[d] + pr[d];
}

__global__ void ln_kernel(const float* __restrict__ x,
                          const float* __restrict__ w, const float* __restrict__ b,
                          __half* __restrict__ yhi, __half* __restrict__ ylo) {
    int row = blockIdx.x;
    const float* xr = x + (size_t)row * Dc;
    __shared__ float r1[256], r2[256];
    float s = 0.f, s2 = 0.f;
    for (int d = threadIdx.x; d < Dc; d += 256) {
        float v = xr[d];
        s += v; s2 += v * v;
    }
    r1[threadIdx.x] = s; r2[threadIdx.x] = s2;
    __syncthreads();
    for (int st = 128; st > 0; st >>= 1) {
        if (threadIdx.x < st) {
            r1[threadIdx.x] += r1[threadIdx.x + st];
            r2[threadIdx.x] += r2[threadIdx.x + st];
        }
        __syncthreads();
    }
    float mean = r1[0] * (1.0f / Dc);
    float var = r2[0] * (1.0f / Dc) - mean * mean;
    float rstd = rsqrtf(var + 1e-5f);
    for (int d = threadIdx.x; d < Dc; d += 256) {
        float v = (xr[d] - mean) * rstd * w[d] + b[d];
        size_t o = (size_t)row * Dc + d;
        split2h(v, yhi + o, ylo + o);
    }
}

// ---------------------------------------------------------------------------
// launcher
// ---------------------------------------------------------------------------
extern "C" void kernel_launch(void* const* d_in, const int* in_sizes, int n_in,
                              void* d_out, int out_size) {
    const int*   ids   = (const int*)d_in[0];
    const float* tok   = (const float*)d_in[1];
    const float* pos   = (const float*)d_in[2];
    const float* Wq    = (const float*)d_in[3];
    const float* bq    = (const float*)d_in[4];
    const float* Wk    = (const float*)d_in[5];
    const float* bk    = (const float*)d_in[6];
    const float* Wv    = (const float*)d_in[7];
    const float* bv    = (const float*)d_in[8];
    const float* Wo    = (const float*)d_in[9];
    const float* bo    = (const float*)d_in[10];
    const float* ln1w  = (const float*)d_in[11];
    const float* ln1b  = (const float*)d_in[12];
    const float* ln2w  = (const float*)d_in[13];
    const float* ln2b  = (const float*)d_in[14];
    const float* Wup   = (const float*)d_in[15];
    const float* bup   = (const float*)d_in[16];
    const float* Wdown = (const float*)d_in[17];
    const float* bdown = (const float*)d_in[18];
    const float* fnw   = (const float*)d_in[19];
    const float* fnb   = (const float*)d_in[20];
    float* out = (float*)d_out;

    float *x;
    __nv_bfloat16 *qkv, *ahi, *alo, *bhi, *blo, *whi, *wlo;
    __half *thi, *tlo;
    cudaGetSymbolAddress((void**)&x, g_x);
    cudaGetSymbolAddress((void**)&qkv, g_qkv);
    cudaGetSymbolAddress((void**)&ahi, g_ahi);
    cudaGetSymbolAddress((void**)&alo, g_alo);
    cudaGetSymbolAddress((void**)&bhi, g_bhi);
    cudaGetSymbolAddress((void**)&blo, g_blo);
    cudaGetSymbolAddress((void**)&whi, g_whi);
    cudaGetSymbolAddress((void**)&wlo, g_wlo);
    cudaGetSymbolAddress((void**)&thi, g_thi);
    cudaGetSymbolAddress((void**)&tlo, g_tlo);
    __nv_bfloat16 *qhi = qkv,              *qlo = qkv + (size_t)MR * Dc;
    __nv_bfloat16 *khi = qkv + 2ull*MR*Dc, *klo = qkv + 3ull*MR*Dc;
    __nv_bfloat16 *vhi = qkv + 4ull*MR*Dc, *vlo = qkv + 5ull*MR*Dc;

    cudaFuncSetAttribute(gemm_t<true,false,true,32>,  cudaFuncAttributeMaxDynamicSharedMemorySize, SMEM_A2W32);
    cudaFuncSetAttribute(gemm_t<true,false,false,32>, cudaFuncAttributeMaxDynamicSharedMemorySize, SMEM_A2W32);
    cudaFuncSetAttribute(gemm_t<true,true,true,32>,   cudaFuncAttributeMaxDynamicSharedMemorySize, SMEM_A2W32);
    cudaFuncSetAttribute(gemm_t<true,false,false,64>, cudaFuncAttributeMaxDynamicSharedMemorySize, SMEM_A2W64);
    cudaFuncSetAttribute(gemm_t<false,false,false,64>,cudaFuncAttributeMaxDynamicSharedMemorySize, SMEM_A1W64);
    cudaFuncSetAttribute(attn_mma, cudaFuncAttributeMaxDynamicSharedMemorySize, ATT_SMEM);

    const dim3 tb32(32, 8);

    embed_kernel<<<MR, 256>>>(ids, tok, pos, x);
    wtrans_sq<<<dim3(Dc / 32, Dc / 32, 4 * Lc), tb32>>>(Wq, Wk, Wv, Wo, whi, wlo);
    wtrans_up<<<dim3(Fc / 32, Dc / 32, Lc), tb32>>>(Wup, whi, wlo);
    wtrans_dn<<<dim3(Dc / 32, Fc / 32, Lc), tb32>>>(Wdown, whi, wlo);
    split_kernel_h<<<(Vc * Dc + 255) / 256, 256>>>(tok, thi, tlo, Vc * Dc);

    const dim3 gmQKV(3 * Dc / 128, MR / 128);   // 24 x 32 (WN=32)
    const dim3 gmD(Dc / 128, MR / 128);         // 8 x 32  (WN=32)
    const dim3 gmF(Fc / 128, MR / 128);         // 32 x 32 (WN=32)
    const dim3 gmD2(Dc / 256, MR / 128);        // 4 x 32  (WN=64)
    const dim3 gmV2(Vc / 256, MR / 128);        // 125 x 32 (WN=64)
    const dim3 gA(Sc / 64, Hc, Bc);

    for (int l = 0; l < Lc; l++) {
        size_t lb = (size_t)l * WPL;
        ln_kernel<<<MR, 256>>>(x, ln1w + l * Dc, ln1b + l * Dc, (__half*)ahi, (__half*)alo);
        gemm_t<true,false,true,32><<<gmQKV, 256, SMEM_A2W32>>>(
            ahi, alo, whi + lb, bq + l * Dc, bk + l * Dc, bv + l * Dc, nullptr,
            nullptr, qkv, nullptr, MR, 3 * Dc, Dc, Dc);
        attn_mma<<<gA, 128, ATT_SMEM>>>(qhi, qlo, khi, klo, vhi, vlo, ahi, alo);
        gemm_t<true,false,false,32><<<gmD, 256, SMEM_A2W32>>>(
            ahi, alo, whi + lb + 3145728, bo + l * Dc, nullptr, nullptr, x,
            x, nullptr, nullptr, MR, Dc, Dc, 0);
        ln_kernel<<<MR, 256>>>(x, ln2w + l * Dc, ln2b + l * Dc, (__half*)ahi, (__half*)alo);
        gemm_t<true,true,true,32><<<gmF, 256, SMEM_A2W32>>>(
            ahi, alo, whi + lb + 4194304, bup + l * Fc, nullptr, nullptr, nullptr,
            nullptr, bhi, blo, MR, Fc, Dc, 0);
        gemm_t<true,false,false,64><<<gmD2, 256, SMEM_A2W64>>>(
            bhi, blo, whi + lb + 8388608, bdown + l * Dc, nullptr, nullptr, x,
            x, nullptr, nullptr, MR, Dc, Fc, 0);
    }

    ln_kernel<<<MR, 256>>>(x, fnw, fnb, (__half*)ahi, (__half*)alo);
    gemm_t<false,false,false,64><<<gmV2, 256, SMEM_A1W64>>>(
        ahi, alo, (const __nv_bfloat16*)thi,
        nullptr, nullptr, nullptr, nullptr, out, nullptr, nullptr, MR, Vc, Dc, 0);
}

// round 15
// speedup vs baseline: 1.1390x; 1.0424x over previous
#include <cuda_runtime.h>
#include <cuda_bf16.h>
#include <cuda_fp16.h>
#include <math.h>
#include <stdint.h>

#define Bc 2
#define Sc 2048
#define Dc 1024
#define Hc 16
#define Lc 6
#define Fc 4096
#define Vc 32000
#define DHc 64
#define MR (Bc*Sc)   // 4096 rows

// ---------------------------------------------------------------------------
// scratch (static device globals; no allocations allowed)
// 16-bit buffers are untyped bit-containers (bf16* alias, hold fp16 bits)
// ---------------------------------------------------------------------------
__device__ float g_x[MR*Dc];
__device__ __nv_bfloat16 g_qkv[6*MR*Dc];   // qhi,qlo,khi,klo,vhi,vlo (fp16 bits)
__device__ __nv_bfloat16 g_ahi[MR*Fc];
__device__ __nv_bfloat16 g_alo[MR*Fc];
__device__ __nv_bfloat16 g_bhi[MR*Fc];
__device__ __nv_bfloat16 g_blo[MR*Fc];
#define WPL 12582912   // elems per layer (4*D*D + D*F + F*D)
__device__ __nv_bfloat16 g_whi[Lc*WPL];    // all weights fp16 bits
__device__ __nv_bfloat16 g_wlo[Lc*WPL];
__device__ __half g_thi[Vc*Dc];
__device__ __half g_tlo[Vc*Dc];

// ---------------------------------------------------------------------------
// helpers
// ---------------------------------------------------------------------------
__device__ __forceinline__ uint32_t s2u(const void* ptr) {
    uint32_t a;
    asm("{ .reg .u64 t; cvta.to.shared.u64 t, %1; cvt.u32.u64 %0, t; }"
        : "=r"(a) : "l"(ptr));
    return a;
}
__device__ __forceinline__ void cpasync16(uint32_t dst, const void* src) {
    asm volatile("cp.async.cg.shared.global [%0], [%1], 16;" :: "r"(dst), "l"(src));
}
__device__ __forceinline__ void ldm4(uint32_t* r, uint32_t addr) {
    asm volatile("ldmatrix.sync.aligned.m8n8.x4.shared.b16 {%0,%1,%2,%3}, [%4];"
                 : "=r"(r[0]), "=r"(r[1]), "=r"(r[2]), "=r"(r[3]) : "r"(addr));
}
__device__ __forceinline__ void ldm4t(uint32_t* r, uint32_t addr) {
    asm volatile("ldmatrix.sync.aligned.m8n8.x4.trans.shared.b16 {%0,%1,%2,%3}, [%4];"
                 : "=r"(r[0]), "=r"(r[1]), "=r"(r[2]), "=r"(r[3]) : "r"(addr));
}
__device__ __forceinline__ void mma16h(float* d, const uint32_t* a, const uint32_t* b) {
    asm volatile(
        "mma.sync.aligned.m16n8k16.row.col.f32.f16.f16.f32 "
        "{%0,%1,%2,%3}, {%4,%5,%6,%7}, {%8,%9}, {%0,%1,%2,%3};"
        : "+f"(d[0]), "+f"(d[1]), "+f"(d[2]), "+f"(d[3])
        : "r"(a[0]), "r"(a[1]), "r"(a[2]), "r"(a[3]), "r"(b[0]), "r"(b[1]));
}
__device__ __forceinline__ void split2h(float v, __half* h, __half* l) {
    __half hh = __float2half(v);
    *h = hh;
    *l = __float2half(v - __half2float(hh));
}
__device__ __forceinline__ void pk2h(float x, float y, uint32_t& hi, uint32_t& lo) {
    __half xh = __float2half(x), yh = __float2half(y);
    __half xl = __float2half(x - __half2float(xh));
    __half yl = __float2half(y - __half2float(yh));
    hi = ((uint32_t)__half_as_ushort(yh) << 16) | __half_as_ushort(xh);
    lo = ((uint32_t)__half_as_ushort(yl) << 16) | __half_as_ushort(xl);
}
__device__ __forceinline__ uint32_t pk1h(float x, float y) {
    __half xh = __float2half(x), yh = __float2half(y);
    return ((uint32_t)__half_as_ushort(yh) << 16) | __half_as_ushort(xh);
}
// fast 2^y on the FMA pipe (y <= 0), err ~2e-6
__device__ __forceinline__ float ex2(float y) {
    y = fmaxf(y, -126.f);
    float fn = y + 12582912.f;
    int n = __float_as_int(fn) - 0x4B400000;
    float r = y - (fn - 12582912.f);
    float p = 1.3333558e-3f;
    p = fmaf(p, r, 9.6181291e-3f);
    p = fmaf(p, r, 5.5504109e-2f);
    p = fmaf(p, r, 2.4022651e-1f);
    p = fmaf(p, r, 6.9314718e-1f);
    p = fmaf(p, r, 1.0f);
    return p * __int_as_float((n + 127) << 23);
}
__device__ __forceinline__ uint32_t swz(uint32_t off) {
    return off ^ ((off >> 3) & 0x70);
}
__device__ __forceinline__ float gelu_f(float v) {
    return 0.5f * v * (1.0f + erff(v * 0.70710678118654752f));
}

// ---------------------------------------------------------------------------
// fp16 split MMA GEMM: C = (Ah[+Al])@Bh^T. K-chunk 64, SW128 smem,
// 3-stage pipeline (single barrier/chunk). TWOA: include Al term.
// WN = warp-N width (32 -> block 128x128, 64 -> block 128x256).
// ---------------------------------------------------------------------------
#define T16 16384                       // one 128x64 16-bit tile (128B rows)

template<int NA, int BROWS>
__device__ __forceinline__ void load_stageG(
    const __nv_bfloat16* A0, const __nv_bfloat16* A1,
    const __nv_bfloat16* B0,
    int K, int k0, uint32_t dbase, int tid) {
#pragma unroll
    for (int t = 0; t < NA; t++) {
        const __nv_bfloat16* s = t ? A1 : A0;
#pragma unroll
        for (int u = 0; u < 4; u++) {
            int id = u * 256 + tid;
            int row = id >> 3, c = id & 7;
            cpasync16(dbase + t * T16 + swz(row * 128 + c * 16),
                      s + (size_t)row * K + k0 + c * 8);
        }
    }
#pragma unroll
    for (int u = 0; u < BROWS / 32; u++) {
        int id = u * 256 + tid;
        int row = id >> 3, c = id & 7;
        cpasync16(dbase + NA * T16 + swz(row * 128 + c * 16),
                  B0 + (size_t)row * K + k0 + c * 8);
    }
}

template<bool TWOA, bool GELU, bool OUT16, int WN>
__global__ __launch_bounds__(256, 1)
void gemm_t(const __nv_bfloat16* __restrict__ Ahi, const __nv_bfloat16* __restrict__ Alo,
            const __nv_bfloat16* __restrict__ Bhi,
            const float* __restrict__ bias, const float* __restrict__ bias2,
            const float* __restrict__ bias3, const float* __restrict__ res,
            float* __restrict__ C, __nv_bfloat16* __restrict__ Chi,
            __nv_bfloat16* __restrict__ Clo, int M, int N, int K, int oseg) {
    constexpr int NA = TWOA ? 2 : 1;
    constexpr int BROWS = 4 * WN;
    constexpr int NTT = WN / 8;
    constexpr int STAGE = (NA * 128 + BROWS) * 128;
    extern __shared__ char smem[];
    const uint32_t sbase = s2u(smem);
    const int tid = threadIdx.x;
    const int warp = tid >> 5, lane = tid & 31;
    const int bm = blockIdx.y * 128, bn = blockIdx.x * BROWS;
    const int wm = (warp >> 2) * 64, wn = (warp & 3) * WN;

    float acc[4][NTT][4];
#pragma unroll
    for (int i = 0; i < 4; i++)
#pragma unroll
        for (int j = 0; j < NTT; j++)
#pragma unroll
            for (int q = 0; q < 4; q++) acc[i][j][q] = 0.f;

    const __nv_bfloat16* A0 = Ahi + (size_t)bm * K;
    const __nv_bfloat16* A1 = Alo + (size_t)bm * K;
    const __nv_bfloat16* B0 = Bhi + (size_t)bn * K;

    const int nch = K >> 6;
    load_stageG<NA, BROWS>(A0, A1, B0, K, 0, sbase, tid);
    asm volatile("cp.async.commit_group;" ::: "memory");
    if (nch > 1) {
        load_stageG<NA, BROWS>(A0, A1, B0, K, 64, sbase + STAGE, tid);
        asm volatile("cp.async.commit_group;" ::: "memory");
    }

    const int g = lane >> 3, r = lane & 7;
    const int a_row = r + (g & 1) * 8;
    const int a_cb  = (g >> 1) * 16;
    const int b_row = (g >> 1) * 8 + r;
    const int b_cb  = (g & 1) * 16;

    for (int c = 0; c < nch; c++) {
        if (c == nch - 1) asm volatile("cp.async.wait_group 0;" ::: "memory");
        else              asm volatile("cp.async.wait_group 1;" ::: "memory");
        __syncthreads();

        uint32_t base = sbase + (c % 3) * STAGE;
#pragma unroll
        for (int ks = 0; ks < 4; ks++) {
            const int kb = ks * 32;
            uint32_t ah[4][4], al[4][4], bh[NTT][2];
#pragma unroll
            for (int mt = 0; mt < 4; mt++) {
                uint32_t ad = base + swz((wm + mt * 16 + a_row) * 128 + kb + a_cb);
                ldm4(ah[mt], ad);
                if (TWOA) ldm4(al[mt], ad + T16);
            }
#pragma unroll
            for (int p = 0; p < WN / 16; p++) {
                uint32_t bd = base + NA * T16 + swz((wn + p * 16 + b_row) * 128 + kb + b_cb);
                uint32_t t4[4];
                ldm4(t4, bd);
                bh[2 * p][0] = t4[0]; bh[2 * p][1] = t4[1];
                bh[2 * p + 1][0] = t4[2]; bh[2 * p + 1][1] = t4[3];
            }
#pragma unroll
            for (int mt = 0; mt < 4; mt++)
#pragma unroll
                for (int nt = 0; nt < NTT; nt++) {
                    mma16h(acc[mt][nt], ah[mt], bh[nt]);
                    if (TWOA) mma16h(acc[mt][nt], al[mt], bh[nt]);
                }
        }
        if (c + 2 < nch) {
            load_stageG<NA, BROWS>(A0, A1, B0, K, (c + 2) * 64,
                                   sbase + ((c + 2) % 3) * STAGE, tid);
            asm volatile("cp.async.commit_group;" ::: "memory");
        }
    }

    // ---- epilogue
    __nv_bfloat16 *chi = Chi, *clo = Clo;
    int ost = N, bnl = bn;
    if (oseg) {
        int t = bn / oseg;
        bnl = bn - t * oseg;
        ost = oseg;
        chi = Chi + (size_t)(2 * t) * M * oseg;
        clo = Chi + (size_t)(2 * t + 1) * M * oseg;
    }
#pragma unroll
    for (int mt = 0; mt < 4; mt++) {
        int r0 = bm + wm + mt * 16 + (lane >> 2);
#pragma unroll
        for (int nt = 0; nt < NTT; nt++) {
            int ccg = bn + wn + nt * 8 + (lane & 3) * 2;
            int ccl = bnl + wn + nt * 8 + (lane & 3) * 2;
            const float* bsel = bias;
            int bidx = ccg;
            if (bias2) {
                if (ccg >= 2 * Dc)      bsel = bias3;
                else if (ccg >= Dc)     bsel = bias2;
                bidx = ccg & (Dc - 1);
            }
            float b0 = bsel ? bsel[bidx] : 0.f, b1 = bsel ? bsel[bidx + 1] : 0.f;
            float v0 = acc[mt][nt][0] + b0, v1 = acc[mt][nt][1] + b1;
            float v2 = acc[mt][nt][2] + b0, v3 = acc[mt][nt][3] + b1;
            if (GELU) {
                v0 = gelu_f(v0); v1 = gelu_f(v1);
                v2 = gelu_f(v2); v3 = gelu_f(v3);
            }
            if (chi) {
                uint32_t h01, l01, h23, l23;
                pk2h(v0, v1, h01, l01);
                pk2h(v2, v3, h23, l23);
                *(uint32_t*)&chi[(size_t)r0 * ost + ccl] = h01;
                *(uint32_t*)&clo[(size_t)r0 * ost + ccl] = l01;
                *(uint32_t*)&chi[(size_t)(r0 + 8) * ost + ccl] = h23;
                *(uint32_t*)&clo[(size_t)(r0 + 8) * ost + ccl] = l23;
            } else {
                if (res) {
                    v0 += res[(size_t)r0 * N + ccg];       v1 += res[(size_t)r0 * N + ccg + 1];
                    v2 += res[(size_t)(r0 + 8) * N + ccg]; v3 += res[(size_t)(r0 + 8) * N + ccg + 1];
                }
                *(float2*)&C[(size_t)r0 * N + ccg] = make_float2(v0, v1);
                *(float2*)&C[(size_t)(r0 + 8) * N + ccg] = make_float2(v2, v3);
            }
        }
    }
}

#define SMEM_A2W32 (3*(256+128)*128)   // 147456
#define SMEM_A2W64 (3*(256+256)*128)   // 196608
#define SMEM_A1W64 (3*(128+256)*128)   // 147456

// ---------------------------------------------------------------------------
// MMA flash attention (fp16, 2-term: qh*(kh+kl), ph*(vh+vl)).
// block = (qt 64 rows, h, b), 4 warps, 64-col k-tiles.
// ---------------------------------------------------------------------------
#define ATT_STAGE 32768
#define ATT_SMEM (2*ATT_STAGE)

__global__ __launch_bounds__(128, 2)
void attn_mma(const __nv_bfloat16* __restrict__ qhi,
              const __nv_bfloat16* __restrict__ khi, const __nv_bfloat16* __restrict__ klo,
              const __nv_bfloat16* __restrict__ vhi, const __nv_bfloat16* __restrict__ vlo,
              __nv_bfloat16* __restrict__ ohi, __nv_bfloat16* __restrict__ olo) {
    extern __shared__ char sm[];
    const uint32_t sb = s2u(sm);
    const int qt = blockIdx.x, h = blockIdx.y, b = blockIdx.z;
    const int tid = threadIdx.x, warp = tid >> 5, lane = tid & 31;
    const int g = lane >> 3, r = lane & 7;
    const int a_row = r + (g & 1) * 8, a_cb = (g >> 1) * 16;
    const int b_row = (g >> 1) * 8 + r, b_cb = (g & 1) * 16;
    const size_t hoff = (size_t)h * 64;
    const size_t rowbase = (size_t)(b * Sc) * Dc;

    // Q hi tile -> smem (stage0 area, reused) -> fragments
    {
        const __nv_bfloat16* src = qhi + rowbase + (size_t)(qt * 64) * Dc + hoff;
#pragma unroll
        for (int u = 0; u < 4; u++) {
            int id = u * 128 + tid;
            int row = id >> 3, c16 = id & 7;
            uint4 val = *(const uint4*)((const char*)(src + (size_t)row * Dc) + c16 * 16);
            *(uint4*)(sm + swz(row * 128 + c16 * 16)) = val;
        }
    }
    __syncthreads();
    uint32_t qh_[4][4];
#pragma unroll
    for (int ks = 0; ks < 4; ks++) {
        uint32_t ad = sb + swz((warp * 16 + a_row) * 128 + ks * 32 + a_cb);
        ldm4(qh_[ks], ad);
    }
    __syncthreads();

    float O[8][4];
#pragma unroll
    for (int i = 0; i < 8; i++)
#pragma unroll
        for (int j = 0; j < 4; j++) O[i][j] = 0.f;
    float m2[2] = {-1e30f, -1e30f};
    float lsum[2] = {0.f, 0.f};

    const __nv_bfloat16* srcs[4] = {khi, klo, vhi, vlo};
#define LOAD_KV(S, KT) do { \
        size_t base_ = rowbase + (size_t)((KT) * 64) * Dc + hoff; \
        uint32_t dst_ = sb + (S) * ATT_STAGE; \
        _Pragma("unroll") \
        for (int t = 0; t < 4; t++) { \
            _Pragma("unroll") \
            for (int u = 0; u < 4; u++) { \
                int id = u * 128 + tid; \
                int row = id >> 3, c16 = id & 7; \
                cpasync16(dst_ + t * 8192 + swz(row * 128 + c16 * 16), \
                          (const char*)(srcs[t] + base_ + (size_t)row * Dc) + c16 * 16); \
            } \
        } \
        asm volatile("cp.async.commit_group;" ::: "memory"); \
    } while (0)

    LOAD_KV(0, 0);

    for (int kt = 0; kt <= qt; kt++) {
        if (kt < qt) {
            LOAD_KV((kt + 1) & 1, kt + 1);
            asm volatile("cp.async.wait_group 1;" ::: "memory");
        } else {
            asm volatile("cp.async.wait_group 0;" ::: "memory");
        }
        __syncthreads();
        const uint32_t kb_ = sb + (kt & 1) * ATT_STAGE;

        float S[8][4];
#pragma unroll
        for (int i = 0; i < 8; i++)
#pragma unroll
            for (int j = 0; j < 4; j++) S[i][j] = 0.f;
#pragma unroll
        for (int ks = 0; ks < 4; ks++) {
#pragma unroll
            for (int p = 0; p < 4; p++) {
                uint32_t t4h[4], t4l[4];
                uint32_t bd = kb_ + swz((p * 16 + b_row) * 128 + ks * 32 + b_cb);
                ldm4(t4h, bd);
                ldm4(t4l, bd + 8192);
                uint32_t bh0[2] = {t4h[0], t4h[1]}, bh1[2] = {t4h[2], t4h[3]};
                uint32_t bl0[2] = {t4l[0], t4l[1]}, bl1[2] = {t4l[2], t4l[3]};
                mma16h(S[2 * p],     qh_[ks], bh0);
                mma16h(S[2 * p],     qh_[ks], bl0);
                mma16h(S[2 * p + 1], qh_[ks], bh1);
                mma16h(S[2 * p + 1], qh_[ks], bl1);
            }
        }
        const float SC = 0.18033688f;
#pragma unroll
        for (int i = 0; i < 8; i++)
#pragma unroll
            for (int j = 0; j < 4; j++) S[i][j] *= SC;
        if (kt == qt) {
            int rr = warp * 16 + (lane >> 2);
#pragma unroll
            for (int nt = 0; nt < 8; nt++) {
                int cc = nt * 8 + (lane & 3) * 2;
                if (cc     > rr)     S[nt][0] = -1e30f;
                if (cc + 1 > rr)     S[nt][1] = -1e30f;
                if (cc     > rr + 8) S[nt][2] = -1e30f;
                if (cc + 1 > rr + 8) S[nt][3] = -1e30f;
            }
        }
        float mx0 = -1e30f, mx1 = -1e30f;
#pragma unroll
        for (int nt = 0; nt < 8; nt++) {
            mx0 = fmaxf(mx0, fmaxf(S[nt][0], S[nt][1]));
            mx1 = fmaxf(mx1, fmaxf(S[nt][2], S[nt][3]));
        }
        mx0 = fmaxf(mx0, __shfl_xor_sync(0xffffffff, mx0, 1));
        mx0 = fmaxf(mx0, __shfl_xor_sync(0xffffffff, mx0, 2));
        mx1 = fmaxf(mx1, __shfl_xor_sync(0xffffffff, mx1, 1));
        mx1 = fmaxf(mx1, __shfl_xor_sync(0xffffffff, mx1, 2));
        float mn0 = fmaxf(m2[0], mx0), mn1 = fmaxf(m2[1], mx1);
        float al0 = ex2(m2[0] - mn0), al1 = ex2(m2[1] - mn1);
        m2[0] = mn0; m2[1] = mn1;
        float s0 = 0.f, s1 = 0.f;
#pragma unroll
        for (int nt = 0; nt < 8; nt++) {
            S[nt][0] = ex2(S[nt][0] - mn0); s0 += S[nt][0];
            S[nt][1] = ex2(S[nt][1] - mn0); s0 += S[nt][1];
            S[nt][2] = ex2(S[nt][2] - mn1); s1 += S[nt][2];
            S[nt][3] = ex2(S[nt][3] - mn1); s1 += S[nt][3];
        }
        s0 += __shfl_xor_sync(0xffffffff, s0, 1);
        s0 += __shfl_xor_sync(0xffffffff, s0, 2);
        s1 += __shfl_xor_sync(0xffffffff, s1, 1);
        s1 += __shfl_xor_sync(0xffffffff, s1, 2);
        lsum[0] = lsum[0] * al0 + s0;
        lsum[1] = lsum[1] * al1 + s1;
#pragma unroll
        for (int nt = 0; nt < 8; nt++) {
            O[nt][0] *= al0; O[nt][1] *= al0;
            O[nt][2] *= al1; O[nt][3] *= al1;
        }
        const uint32_t vb = kb_ + 16384;
#pragma unroll
        for (int ks = 0; ks < 4; ks++) {
            uint32_t pah[4];
            pah[0] = pk1h(S[2 * ks][0],     S[2 * ks][1]);
            pah[1] = pk1h(S[2 * ks][2],     S[2 * ks][3]);
            pah[2] = pk1h(S[2 * ks + 1][0], S[2 * ks + 1][1]);
            pah[3] = pk1h(S[2 * ks + 1][2], S[2 * ks + 1][3]);
#pragma unroll
            for (int dg = 0; dg < 4; dg++) {
                uint32_t th[4], tl[4];
                uint32_t vd = vb + swz((ks * 16 + (lane & 15)) * 128 + dg * 32 + (lane >> 4) * 16);
                ldm4t(th, vd);
                ldm4t(tl, vd + 8192);
                uint32_t bh0[2] = {th[0], th[1]}, bh1[2] = {th[2], th[3]};
                uint32_t bl0[2] = {tl[0], tl[1]}, bl1[2] = {tl[2], tl[3]};
                mma16h(O[2 * dg],     pah, bh0);
                mma16h(O[2 * dg],     pah, bl0);
                mma16h(O[2 * dg + 1], pah, bh1);
                mma16h(O[2 * dg + 1], pah, bl1);
            }
        }
        __syncthreads();
    }

    float inv0 = 1.f / lsum[0], inv1 = 1.f / lsum[1];
    int r0 = qt * 64 + warp * 16 + (lane >> 2);
#pragma unroll
    for (int nt = 0; nt < 8; nt++) {
        int cc = nt * 8 + (lane & 3) * 2;
        size_t o0 = rowbase + (size_t)r0 * Dc + hoff + cc;
        size_t o1 = o0 + (size_t)8 * Dc;
        uint32_t h01, l01, h23, l23;
        pk2h(O[nt][0] * inv0, O[nt][1] * inv0, h01, l01);
        pk2h(O[nt][2] * inv1, O[nt][3] * inv1, h23, l23);
        *(uint32_t*)&ohi[o0] = h01; *(uint32_t*)&olo[o0] = l01;
        *(uint32_t*)&ohi[o1] = h23; *(uint32_t*)&olo[o1] = l23;
    }
}

// ---------------------------------------------------------------------------
// prep kernels (batched over layer x matrix via blockIdx.z)
// ---------------------------------------------------------------------------
__device__ __forceinline__ void wtrans_body(const float* W, __half* hi, __half* lo,
                                            int K, int N) {
    __shared__ float t[32][33];
    int n0 = blockIdx.x * 32, k0 = blockIdx.y * 32;
    int tx = threadIdx.x, ty = threadIdx.y;
#pragma unroll
    for (int r = 0; r < 4; r++)
        t[ty + r * 8][tx] = W[(size_t)(k0 + ty + r * 8) * N + n0 + tx];
    __syncthreads();
#pragma unroll
    for (int r = 0; r < 4; r++) {
        int a = ty + r * 8;
        float v = t[tx][a];
        size_t o = (size_t)(n0 + a) * K + k0 + tx;
        split2h(v, hi + o, lo + o);
    }
}

__global__ void wtrans_sq(const float* __restrict__ Wq, const float* __restrict__ Wk,
                          const float* __restrict__ Wv, const float* __restrict__ Wo,
                          __nv_bfloat16* __restrict__ whi, __nv_bfloat16* __restrict__ wlo) {
    int z = blockIdx.z, l = z >> 2, m = z & 3;
    const float* srcs[4] = {Wq, Wk, Wv, Wo};
    const float* W = srcs[m] + (size_t)l * Dc * Dc;
    size_t off = (size_t)l * WPL + (size_t)m * 1048576;
    wtrans_body(W, (__half*)(whi + off), (__half*)(wlo + off), Dc, Dc);
}
__global__ void wtrans_up(const float* __restrict__ Wup,
                          __nv_bfloat16* __restrict__ whi, __nv_bfloat16* __restrict__ wlo) {
    int l = blockIdx.z;
    size_t off = (size_t)l * WPL + 4194304;
    wtrans_body(Wup + (size_t)l * Dc * Fc, (__half*)(whi + off), (__half*)(wlo + off), Dc, Fc);
}
__global__ void wtrans_dn(const float* __restrict__ Wdown,
                          __nv_bfloat16* __restrict__ whi, __nv_bfloat16* __restrict__ wlo) {
    int l = blockIdx.z;
    size_t off = (size_t)l * WPL + 8388608;
    wtrans_body(Wdown + (size_t)l * Fc * Dc, (__half*)(whi + off), (__half*)(wlo + off), Fc, Dc);
}

__global__ void split_kernel_h(const float* __restrict__ in,
                               __half* __restrict__ hi,
                               __half* __restrict__ lo, int n) {
    int i = blockIdx.x * 256 + threadIdx.x;
    if (i < n) split2h(in[i], &hi[i], &lo[i]);
}

__global__ void embed_kernel(const int* __restrict__ ids,
                             const float* __restrict__ tok,
                             const float* __restrict__ pos,
                             float* __restrict__ x) {
    int row = blockIdx.x;
    int s = row % Sc;
    int id = ids[row];
    const float* tr = tok + (size_t)id * Dc;
    const float* pr = pos + (size_t)s * Dc;
    float* xr = x + (size_t)row * Dc;
    for (int d = threadIdx.x; d < Dc; d += blockDim.x) xr[d] = tr[d] + pr[d];
}

__global__ void ln_kernel(const float* __restrict__ x,
                          const float* __restrict__ w, const float* __restrict__ b,
                          __half* __restrict__ yhi, __half* __restrict__ ylo) {
    int row = blockIdx.x;
    const float* xr = x + (size_t)row * Dc;
    __shared__ float r1[256], r2[256];
    float s = 0.f, s2 = 0.f;
    for (int d = threadIdx.x; d < Dc; d += 256) {
        float v = xr[d];
        s += v; s2 += v * v;
    }
    r1[threadIdx.x] = s; r2[threadIdx.x] = s2;
    __syncthreads();
    for (int st = 128; st > 0; st >>= 1) {
        if (threadIdx.x < st) {
            r1[threadIdx.x] += r1[threadIdx.x + st];
            r2[threadIdx.x] += r2[threadIdx.x + st];
        }
        __syncthreads();
    }
    float mean = r1[0] * (1.0f / Dc);
    float var = r2[0] * (1.0f / Dc) - mean * mean;
    float rstd = rsqrtf(var + 1e-5f);
    for (int d = threadIdx.x; d < Dc; d += 256) {
        float v = (xr[d] - mean) * rstd * w[d] + b[d];
        size_t o = (size_t)row * Dc + d;
        split2h(v, yhi + o, ylo + o);
    }
}

// ---------------------------------------------------------------------------
// launcher
// ---------------------------------------------------------------------------
extern "C" void kernel_launch(void* const* d_in, const int* in_sizes, int n_in,
                              void* d_out, int out_size) {
    const int*   ids   = (const int*)d_in[0];
    const float* tok   = (const float*)d_in[1];
    const float* pos   = (const float*)d_in[2];
    const float* Wq    = (const float*)d_in[3];
    const float* bq    = (const float*)d_in[4];
    const float* Wk    = (const float*)d_in[5];
    const float* bk    = (const float*)d_in[6];
    const float* Wv    = (const float*)d_in[7];
    const float* bv    = (const float*)d_in[8];
    const float* Wo    = (const float*)d_in[9];
    const float* bo    = (const float*)d_in[10];
    const float* ln1w  = (const float*)d_in[11];
    const float* ln1b  = (const float*)d_in[12];
    const float* ln2w  = (const float*)d_in[13];
    const float* ln2b  = (const float*)d_in[14];
    const float* Wup   = (const float*)d_in[15];
    const float* bup   = (const float*)d_in[16];
    const float* Wdown = (const float*)d_in[17];
    const float* bdown = (const float*)d_in[18];
    const float* fnw   = (const float*)d_in[19];
    const float* fnb   = (const float*)d_in[20];
    float* out = (float*)d_out;

    float *x;
    __nv_bfloat16 *qkv, *ahi, *alo, *bhi, *blo, *whi, *wlo;
    __half *thi, *tlo;
    cudaGetSymbolAddress((void**)&x, g_x);
    cudaGetSymbolAddress((void**)&qkv, g_qkv);
    cudaGetSymbolAddress((void**)&ahi, g_ahi);
    cudaGetSymbolAddress((void**)&alo, g_alo);
    cudaGetSymbolAddress((void**)&bhi, g_bhi);
    cudaGetSymbolAddress((void**)&blo, g_blo);
    cudaGetSymbolAddress((void**)&whi, g_whi);
    cudaGetSymbolAddress((void**)&wlo, g_wlo);
    cudaGetSymbolAddress((void**)&thi, g_thi);
    cudaGetSymbolAddress((void**)&tlo, g_tlo);
    __nv_bfloat16 *qhi = qkv;
    __nv_bfloat16 *khi = qkv + 2ull*MR*Dc, *klo = qkv + 3ull*MR*Dc;
    __nv_bfloat16 *vhi = qkv + 4ull*MR*Dc, *vlo = qkv + 5ull*MR*Dc;

    cudaFuncSetAttribute(gemm_t<true,false,true,32>,  cudaFuncAttributeMaxDynamicSharedMemorySize, SMEM_A2W32);
    cudaFuncSetAttribute(gemm_t<true,false,false,32>, cudaFuncAttributeMaxDynamicSharedMemorySize, SMEM_A2W32);
    cudaFuncSetAttribute(gemm_t<true,true,true,32>,   cudaFuncAttributeMaxDynamicSharedMemorySize, SMEM_A2W32);
    cudaFuncSetAttribute(gemm_t<true,false,false,64>, cudaFuncAttributeMaxDynamicSharedMemorySize, SMEM_A2W64);
    cudaFuncSetAttribute(gemm_t<false,false,false,64>,cudaFuncAttributeMaxDynamicSharedMemorySize, SMEM_A1W64);
    cudaFuncSetAttribute(attn_mma, cudaFuncAttributeMaxDynamicSharedMemorySize, ATT_SMEM);

    const dim3 tb32(32, 8);

    embed_kernel<<<MR, 256>>>(ids, tok, pos, x);
    wtrans_sq<<<dim3(Dc / 32, Dc / 32, 4 * Lc), tb32>>>(Wq, Wk, Wv, Wo, whi, wlo);
    wtrans_up<<<dim3(Fc / 32, Dc / 32, Lc), tb32>>>(Wup, whi, wlo);
    wtrans_dn<<<dim3(Dc / 32, Fc / 32, Lc), tb32>>>(Wdown, whi, wlo);
    split_kernel_h<<<(Vc * Dc + 255) / 256, 256>>>(tok, thi, tlo, Vc * Dc);

    const dim3 gmQKV(3 * Dc / 128, MR / 128);   // 24 x 32 (WN=32)
    const dim3 gmD(Dc / 128, MR / 128);         // 8 x 32  (WN=32)
    const dim3 gmF(Fc / 128, MR / 128);         // 32 x 32 (WN=32)
    const dim3 gmD2(Dc / 256, MR / 128);        // 4 x 32  (WN=64)
    const dim3 gmV2(Vc / 256, MR / 128);        // 125 x 32 (WN=64)
    const dim3 gA(Sc / 64, Hc, Bc);

    for (int l = 0; l < Lc; l++) {
        size_t lb = (size_t)l * WPL;
        ln_kernel<<<MR, 256>>>(x, ln1w + l * Dc, ln1b + l * Dc, (__half*)ahi, (__half*)alo);
        gemm_t<true,false,true,32><<<gmQKV, 256, SMEM_A2W32>>>(
            ahi, alo, whi + lb, bq + l * Dc, bk + l * Dc, bv + l * Dc, nullptr,
            nullptr, qkv, nullptr, MR, 3 * Dc, Dc, Dc);
        attn_mma<<<gA, 128, ATT_SMEM>>>(qhi, khi, klo, vhi, vlo, ahi, alo);
        gemm_t<true,false,false,32><<<gmD, 256, SMEM_A2W32>>>(
            ahi, alo, whi + lb + 3145728, bo + l * Dc, nullptr, nullptr, x,
            x, nullptr, nullptr, MR, Dc, Dc, 0);
        ln_kernel<<<MR, 256>>>(x, ln2w + l * Dc, ln2b + l * Dc, (__half*)ahi, (__half*)alo);
        gemm_t<true,true,true,32><<<gmF, 256, SMEM_A2W32>>>(
            ahi, alo, whi + lb + 4194304, bup + l * Fc, nullptr, nullptr, nullptr,
            nullptr, bhi, blo, MR, Fc, Dc, 0);
        gemm_t<true,false,false,64><<<gmD2, 256, SMEM_A2W64>>>(
            bhi, blo, whi + lb + 8388608, bdown + l * Dc, nullptr, nullptr, x,
            x, nullptr, nullptr, MR, Dc, Fc, 0);
    }

    ln_kernel<<<MR, 256>>>(x, fnw, fnb, (__half*)ahi, (__half*)alo);
    gemm_t<false,false,false,64><<<gmV2, 256, SMEM_A1W64>>>(
        ahi, alo, (const __nv_bfloat16*)thi,
        nullptr, nullptr, nullptr, nullptr, out, nullptr, nullptr, MR, Vc, Dc, 0);
}